// round 5
// baseline (speedup 1.0000x reference)
#include <cuda_runtime.h>
#include <cstdint>

#define Bg 8
#define Nn 2048
#define NB (Bg*Nn)          // 16384 rows
#define Kc 100
#define MAXD 640
#define CHUNK 256

// ---------------- device scratch (no runtime allocation allowed) ----------------
__device__ int   g_col[NB*MAXD];
__device__ float g_val[NB*MAXD];
__device__ int   g_cnt[NB];
__device__ float g_self[NB];     // 1.0 if diag==0 else 0.0
__device__ float g_dinvw[NB];
__device__ float g_dinvb[NB];

__device__ float g_T[NB*130];    // transformed features fed to SpMM
__device__ float g_pre[NB*130];  // pre-BN SpMM output

__device__ float g_x11[NB*30], g_x12[NB*30], g_x13[NB*30];
__device__ float g_s11[NB*30], g_s12[NB*30], g_s13[NB*100];
__device__ float g_sm [NB*100];      // softmax assignments
__device__ float g_adjs[NB*100];     // adj @ s

__device__ float g_p1x  [Bg*100*30];
__device__ float g_p1adj[Bg*100*100];
__device__ float g_A2   [Bg*100*100];
__device__ float g_pre21[Bg*100*30], g_pre22[Bg*100*30], g_pre23[Bg*100*30];
__device__ float g_x1out[Bg*90], g_x2out[Bg*90];

// stats layout: per layer [sum(C) | sumsq(C)]
// L1 @0 (C=60), L2 @120 (C=60), L3 @240 (C=130), S2a @500, S2b @560, S2c @620 (C=30)
#define STATS_TOTAL 680
__device__ float g_stats[STATS_TOTAL];

// ---------------- kernels ----------------
__global__ void k_zero_stats() {
    int i = blockIdx.x*blockDim.x + threadIdx.x;
    if (i < STATS_TOTAL) g_stats[i] = 0.f;
}

// Build ELL + degrees. grid (2048, 8), block 256.
__global__ void k_build(const float* __restrict__ adj) {
    int i = blockIdx.x, b = blockIdx.y;
    int row = b*Nn + i;
    const float* arow = adj + (size_t)row * Nn;
    __shared__ int s_cnt;
    __shared__ float s_diag;
    __shared__ float red[256];
    int tid = threadIdx.x;
    if (tid == 0) { s_cnt = 0; s_diag = 0.f; }
    __syncthreads();
    float wsum = 0.f;
    int base = row * MAXD;
    for (int j = tid; j < Nn; j += 256) {
        float a = arow[j];
        if (j == i) s_diag = a;
        if (a != 0.f) {
            wsum += a;
            int pos = atomicAdd(&s_cnt, 1);
            if (pos < MAXD) { g_col[base+pos] = j; g_val[base+pos] = a; }
        }
    }
    red[tid] = wsum;
    __syncthreads();
    for (int s = 128; s > 0; s >>= 1) { if (tid < s) red[tid] += red[tid+s]; __syncthreads(); }
    if (tid == 0) {
        int cnt = s_cnt;
        float d0 = (s_diag == 0.f) ? 1.f : 0.f;
        g_cnt[row]  = cnt < MAXD ? cnt : MAXD;
        g_self[row] = d0;
        float degw = red[0] + d0;
        float degb = (float)cnt + d0;
        g_dinvw[row] = degw > 0.f ? rsqrtf(degw) : 0.f;
        g_dinvb[row] = degb > 0.f ? rsqrtf(degb) : 0.f;
    }
}

// layer-1 feature transform: T[:, :30] = dinvw * (x @ Win0); T[:, 30:60] = dinvb * (x @ Win1)
__global__ void k_transform1(const float* __restrict__ x, const float* __restrict__ Win) {
    int idx = blockIdx.x*blockDim.x + threadIdx.x;
    if (idx >= NB*60) return;
    int row = idx / 60, c = idx % 60;
    float x0 = x[row*3], x1 = x[row*3+1], x2 = x[row*3+2];
    float t;
    if (c < 30) t = (x0*Win[c] + x1*Win[30+c] + x2*Win[60+c]) * g_dinvw[row];
    else { int c2 = c-30; t = (x0*Win[90+c2] + x1*Win[120+c2] + x2*Win[150+c2]) * g_dinvb[row]; }
    g_T[(size_t)row*60 + c] = t;
}

// fused dual SpMM: first CX channels weighted+normalized, next CS channels binary+normalized
// blockDim = CX+CS, grid = NB
__global__ void k_spmm_dual(int CX, int CS, const float* __restrict__ biasX, const float* __restrict__ biasS) {
    int row = blockIdx.x;
    int Ct = CX + CS;
    int c = threadIdx.x;
    int bbase = (row >> 11) << 11;
    __shared__ int   s_col[CHUNK];
    __shared__ float s_val[CHUNK];
    bool isX = (c < CX);
    float acc = g_self[row] * g_T[(size_t)row*Ct + c];
    int cnt = g_cnt[row];
    int base = row * MAXD;
    for (int k0 = 0; k0 < cnt; k0 += CHUNK) {
        int m = cnt - k0; if (m > CHUNK) m = CHUNK;
        __syncthreads();
        for (int t = c; t < m; t += Ct) { s_col[t] = g_col[base+k0+t]; s_val[t] = g_val[base+k0+t]; }
        __syncthreads();
        #pragma unroll 4
        for (int k = 0; k < m; k++) {
            int col = s_col[k];
            float w = isX ? s_val[k] : 1.0f;
            acc += w * g_T[(size_t)(bbase + col)*Ct + c];
        }
    }
    float dinv = isX ? g_dinvw[row] : g_dinvb[row];
    float bias = isX ? biasX[c] : biasS[c-CX];
    g_pre[(size_t)row*Ct + c] = acc * dinv + bias;
}

// adj @ s (raw weighted, no self-loop, no normalization). blockDim=100
__global__ void k_adjs() {
    int row = blockIdx.x;
    int c = threadIdx.x;
    int bbase = (row >> 11) << 11;
    __shared__ int   s_col[CHUNK];
    __shared__ float s_val[CHUNK];
    float acc = 0.f;
    int cnt = g_cnt[row];
    int base = row * MAXD;
    for (int k0 = 0; k0 < cnt; k0 += CHUNK) {
        int m = cnt - k0; if (m > CHUNK) m = CHUNK;
        __syncthreads();
        for (int t = c; t < m; t += 100) { s_col[t] = g_col[base+k0+t]; s_val[t] = g_val[base+k0+t]; }
        __syncthreads();
        #pragma unroll 4
        for (int k = 0; k < m; k++)
            acc += s_val[k] * g_sm[(size_t)(bbase + s_col[k])*100 + c];
    }
    g_adjs[(size_t)row*100 + c] = acc;
}

// BN stats over g_pre: grid 128, block 256, dynamic shared 2*C floats
__global__ void k_stats(int C, int off) {
    extern __shared__ float sh[];
    int tid = threadIdx.x;
    for (int i = tid; i < 2*C; i += blockDim.x) sh[i] = 0.f;
    __syncthreads();
    int total = NB*C;
    for (int idx = blockIdx.x*blockDim.x + tid; idx < total; idx += gridDim.x*blockDim.x) {
        float v = g_pre[idx];
        int c = idx % C;
        atomicAdd(&sh[c], v);
        atomicAdd(&sh[C+c], v*v);
    }
    __syncthreads();
    for (int i = tid; i < 2*C; i += blockDim.x) atomicAdd(&g_stats[off+i], sh[i]);
}

// apply BN -> store branch outputs -> compute next layer's transformed T. grid NB, block 160.
__global__ void k_apply(int layer,
                        const float* __restrict__ gamma30, const float* __restrict__ beta30,
                        const float* __restrict__ gamma100, const float* __restrict__ beta100,
                        const float* __restrict__ W3030, const float* __restrict__ Wp13)
{
    int CxIn, CsIn, off, CoutX = 0, CoutS = 0, doNext;
    const float *gX, *bX, *gS, *bS, *Wx = nullptr, *Ws = nullptr;
    float *outX, *outS;
    if (layer == 1) {
        CxIn=30; CsIn=30; off=0;   gX=gamma30;    bX=beta30;    gS=gamma30+90;  bS=beta30+90;
        outX=g_x11; outS=g_s11; Wx=W3030;      Ws=W3030+1800; CoutX=30; CoutS=30;  doNext=1;
    } else if (layer == 2) {
        CxIn=30; CsIn=30; off=120; gX=gamma30+30; bX=beta30+30; gS=gamma30+120; bS=beta30+120;
        outX=g_x12; outS=g_s12; Wx=W3030+900;  Ws=Wp13;       CoutX=30; CoutS=100; doNext=1;
    } else {
        CxIn=30; CsIn=100; off=240; gX=gamma30+60; bX=beta30+60; gS=gamma100;   bS=beta100;
        outX=g_x13; outS=g_s13; doNext=0;
    }
    int row = blockIdx.x;
    int Cin = CxIn + CsIn;
    __shared__ float sh[132];
    int tid = threadIdx.x;
    const float invM = 1.0f / (float)NB;
    if (tid < Cin) {
        float sum = g_stats[off + tid], sq = g_stats[off + Cin + tid];
        float mean = sum * invM;
        float var  = fmaxf(sq * invM - mean*mean, 0.f);
        float g, bb;
        if (tid < CxIn) { g = gX[tid]; bb = bX[tid]; }
        else            { g = gS[tid-CxIn]; bb = bS[tid-CxIn]; }
        float v = (g_pre[(size_t)row*Cin + tid] - mean) * rsqrtf(var + 1e-5f) * g + bb;
        sh[tid] = v;
        if (tid < CxIn) outX[(size_t)row*CxIn + tid] = v;
        else            outS[(size_t)row*CsIn + tid - CxIn] = v;
    }
    if (!doNext) return;
    __syncthreads();
    int Cout = CoutX + CoutS;
    if (tid < Cout) {
        float t = 0.f;
        if (tid < CoutX) {
            #pragma unroll 6
            for (int k = 0; k < CxIn; k++) t += sh[k]*Wx[k*CoutX + tid];
            t *= g_dinvw[row];
        } else {
            int c2 = tid - CoutX;
            #pragma unroll 6
            for (int k = 0; k < CsIn; k++) t += sh[CxIn + k]*Ws[k*CoutS + c2];
            t *= g_dinvb[row];
        }
        g_T[(size_t)row*Cout + tid] = t;
    }
}

// s1 = [s11|s12|s13] @ Wfc + bfc, then softmax. grid NB, block 128.
__global__ void k_s1softmax(const float* __restrict__ Wfc, const float* __restrict__ bfc) {
    int row = blockIdx.x;
    __shared__ float sin[160];
    __shared__ float red[128];
    int tid = threadIdx.x;
    if (tid < 30) { sin[tid] = g_s11[row*30+tid]; sin[30+tid] = g_s12[row*30+tid]; }
    if (tid < 100) sin[60+tid] = g_s13[(size_t)row*100+tid];
    __syncthreads();
    float z = -1e30f;
    if (tid < 100) {
        float acc = bfc[tid];
        #pragma unroll 8
        for (int k = 0; k < 160; k++) acc += sin[k]*Wfc[k*100+tid];
        z = acc;
    }
    red[tid] = z;
    __syncthreads();
    for (int s = 64; s > 0; s >>= 1) { if (tid < s) red[tid] = fmaxf(red[tid], red[tid+s]); __syncthreads(); }
    float mx = red[0];
    __syncthreads();
    float e = (tid < 100) ? expf(z - mx) : 0.f;
    red[tid] = e;
    __syncthreads();
    for (int s = 64; s > 0; s >>= 1) { if (tid < s) red[tid] += red[tid+s]; __syncthreads(); }
    float inv = 1.0f / red[0];
    if (tid < 100) g_sm[(size_t)row*100 + tid] = e * inv;
}

// C[b,m,l] = sum_n s[b,n,m] * B[b,n,l]; mode 0: B=g_adjs CB=100 -> p1adj; mode 1: B=g_x13 CB=30 -> p1x
__global__ void k_gemmTN(int mode) {
    int CB = mode == 0 ? 100 : 30;
    const float* Bm = mode == 0 ? g_adjs : g_x13;
    float* C = mode == 0 ? g_p1adj : g_p1x;
    int b = blockIdx.z;
    int m0 = blockIdx.y*16, l0 = blockIdx.x*16;
    int tx = threadIdx.x, ty = threadIdx.y;
    __shared__ float As[16][17], Bs[16][17];
    const float* Ab = g_sm + (size_t)b*Nn*100;
    const float* Bb = Bm  + (size_t)b*Nn*CB;
    float acc = 0.f;
    for (int n0 = 0; n0 < Nn; n0 += 16) {
        int am = m0 + tx;
        As[ty][tx] = (am < 100) ? Ab[(n0+ty)*100 + am] : 0.f;
        int bl = l0 + tx;
        Bs[ty][tx] = (bl < CB) ? Bb[(n0+ty)*CB + bl] : 0.f;
        __syncthreads();
        #pragma unroll
        for (int i = 0; i < 16; i++) acc += As[i][ty]*Bs[i][tx];
        __syncthreads();
    }
    int m = m0+ty, l = l0+tx;
    if (m < 100 && l < CB) C[((size_t)b*100 + m)*CB + l] = acc;
}

// normalize pooled adjacency. grid 8, block 128.
__global__ void k_A2() {
    int b = blockIdx.x;
    const float* p = g_p1adj + b*10000;
    __shared__ float dinv[100], sflag[100];
    int tid = threadIdx.x;
    if (tid < 100) {
        float s = 0.f;
        float diag = p[tid*100+tid];
        for (int j = 0; j < 100; j++) s += p[tid*100+j];
        float d0 = (diag == 0.f) ? 1.f : 0.f;
        float deg = s + d0;
        dinv[tid] = deg > 0.f ? rsqrtf(deg) : 0.f;
        sflag[tid] = d0;
    }
    __syncthreads();
    for (int idx = tid; idx < 10000; idx += blockDim.x) {
        int i = idx/100, j = idx%100;
        float v = p[idx] + ((i == j) ? sflag[i] : 0.f);
        g_A2[b*10000+idx] = dinv[i]*v*dinv[j];
    }
}

// stage-2 conv: out = A2 @ (BN(in) @ W) + bias, with stats accumulation. grid (8,5), block 256.
__global__ void k_conv2(int mode,
                        const float* __restrict__ gamma30, const float* __restrict__ beta30,
                        const float* __restrict__ W3030, const float* __restrict__ b30)
{
    const float *in, *W, *bias, *gR = nullptr, *bR = nullptr;
    float* outPre; int useBN, offIn = 0, offOut;
    if (mode == 0) { in=g_p1x;  useBN=0;            outPre=g_pre21; offOut=500; W=W3030+2700; bias=b30+150; }
    else if (mode == 1) { in=g_pre21; useBN=1; offIn=500; gR=gamma30+150; bR=beta30+150;
                          outPre=g_pre22; offOut=560; W=W3030+3600; bias=b30+180; }
    else { in=g_pre22; useBN=1; offIn=560; gR=gamma30+180; bR=beta30+180;
           outPre=g_pre23; offOut=620; W=W3030+4500; bias=b30+210; }
    int b = blockIdx.x, chunk = blockIdx.y;
    __shared__ float shin[3000], shtmp[3000];
    __shared__ float scale[30], shift[30], ss[30], sq[30];
    int tid = threadIdx.x;
    if (tid < 30) {
        ss[tid] = 0.f; sq[tid] = 0.f;
        if (useBN) {
            float sum = g_stats[offIn+tid], q = g_stats[offIn+30+tid];
            float m = sum*(1.f/800.f);
            float v = fmaxf(q*(1.f/800.f) - m*m, 0.f);
            float sc = rsqrtf(v+1e-5f)*gR[tid];
            scale[tid] = sc; shift[tid] = bR[tid] - m*sc;
        } else { scale[tid] = 1.f; shift[tid] = 0.f; }
    }
    __syncthreads();
    for (int idx = tid; idx < 3000; idx += 256) {
        int c = idx % 30;
        shin[idx] = in[b*3000+idx]*scale[c] + shift[c];
    }
    __syncthreads();
    for (int idx = tid; idx < 3000; idx += 256) {
        int j = idx/30, c = idx%30;
        float t = 0.f;
        #pragma unroll 6
        for (int k = 0; k < 30; k++) t += shin[j*30+k]*W[k*30+c];
        shtmp[idx] = t;
    }
    __syncthreads();
    const float* A2b = g_A2 + b*10000;
    for (int idx = tid; idx < 600; idx += 256) {
        int il = idx/30, c = idx%30;
        int i = chunk*20 + il;
        float acc = bias[c];
        const float* arow = A2b + i*100;
        #pragma unroll 4
        for (int j = 0; j < 100; j++) acc += arow[j]*shtmp[j*30+c];
        outPre[b*3000 + i*30 + c] = acc;
        atomicAdd(&ss[c], acc);
        atomicAdd(&sq[c], acc*acc);
    }
    __syncthreads();
    if (tid < 30) {
        atomicAdd(&g_stats[offOut+tid], ss[tid]);
        atomicAdd(&g_stats[offOut+30+tid], sq[tid]);
    }
}

// stage-1 max pool: x1_out[b, c] = max_n [x11|x12|x13]. grid 8, block 96.
__global__ void k_max1() {
    int b = blockIdx.x, c = threadIdx.x;
    if (c >= 90) return;
    int which = c/30, cc = c%30;
    const float* buf = which == 0 ? g_x11 : which == 1 ? g_x12 : g_x13;
    const float* p = buf + (size_t)b*Nn*30 + cc;
    float m = -3.4e38f;
    #pragma unroll 8
    for (int n = 0; n < Nn; n++) m = fmaxf(m, p[n*30]);
    g_x1out[b*90+c] = m;
}

// stage-2 max pool with lazy BN apply. grid 8, block 96.
__global__ void k_max2(const float* __restrict__ gamma30, const float* __restrict__ beta30) {
    int b = blockIdx.x, c = threadIdx.x;
    if (c >= 90) return;
    int which = c/30, cc = c%30;
    const float* buf = which == 0 ? g_pre21 : which == 1 ? g_pre22 : g_pre23;
    int off = 500 + which*60;
    float sum = g_stats[off+cc], q = g_stats[off+30+cc];
    float mn = sum*(1.f/800.f);
    float var = fmaxf(q*(1.f/800.f) - mn*mn, 0.f);
    float g  = gamma30[(5+which)*30+cc];
    float be = beta30 [(5+which)*30+cc];
    float sc = rsqrtf(var+1e-5f)*g;
    float sh = be - mn*sc;
    const float* p = buf + b*3000 + cc;
    float m = -3.4e38f;
    #pragma unroll 4
    for (int k = 0; k < 100; k++) m = fmaxf(m, p[k*30]*sc + sh);
    g_x2out[b*90+c] = m;
}

// final MLP. grid 8, block 192.
__global__ void k_final(const float* __restrict__ W1, const float* __restrict__ b1,
                        const float* __restrict__ W2, const float* __restrict__ b2,
                        float* __restrict__ out)
{
    int b = blockIdx.x, tid = threadIdx.x;
    __shared__ float sh[180];
    __shared__ float hh[50];
    if (tid < 90) sh[tid] = g_x1out[b*90+tid];
    else if (tid < 180) sh[tid] = g_x2out[b*90 + tid - 90];
    __syncthreads();
    if (tid < 50) {
        float acc = b1[tid];
        #pragma unroll 4
        for (int k = 0; k < 180; k++) acc += sh[k]*W1[k*50+tid];
        hh[tid] = fmaxf(acc, 0.f);
    }
    __syncthreads();
    if (tid < 6) {
        float acc = b2[tid];
        #pragma unroll
        for (int k = 0; k < 50; k++) acc += hh[k]*W2[k*6+tid];
        out[b*6+tid] = acc;
    }
}

// ---------------- host launch ----------------
extern "C" void kernel_launch(void* const* d_in, const int* in_sizes, int n_in,
                              void* d_out, int out_size) {
    const float* x        = (const float*)d_in[0];
    const float* adj      = (const float*)d_in[1];
    const float* W_in     = (const float*)d_in[2];
    const float* W3030    = (const float*)d_in[3];
    const float* Wp13     = (const float*)d_in[4];
    const float* b30      = (const float*)d_in[5];
    const float* b100     = (const float*)d_in[6];
    const float* Wfc      = (const float*)d_in[7];
    const float* bfc      = (const float*)d_in[8];
    const float* W1       = (const float*)d_in[9];
    const float* b1       = (const float*)d_in[10];
    const float* W2       = (const float*)d_in[11];
    const float* b2       = (const float*)d_in[12];
    const float* gamma30  = (const float*)d_in[13];
    const float* beta30   = (const float*)d_in[14];
    const float* gamma100 = (const float*)d_in[15];
    const float* beta100  = (const float*)d_in[16];
    float* out = (float*)d_out;

    k_zero_stats<<<3, 256>>>();
    k_build<<<dim3(Nn, Bg), 256>>>(adj);
    k_transform1<<<(NB*60 + 255)/256, 256>>>(x, W_in);

    // layer 1 (x11 weighted 30ch | s11 binary 30ch)
    k_spmm_dual<<<NB, 60>>>(30, 30, b30 + 0, b30 + 90);
    k_stats<<<128, 256, 2*60*sizeof(float)>>>(60, 0);
    k_apply<<<NB, 160>>>(1, gamma30, beta30, gamma100, beta100, W3030, Wp13);

    // layer 2 (x12 | s12)
    k_spmm_dual<<<NB, 60>>>(30, 30, b30 + 30, b30 + 120);
    k_stats<<<128, 256, 2*60*sizeof(float)>>>(60, 120);
    k_apply<<<NB, 160>>>(2, gamma30, beta30, gamma100, beta100, W3030, Wp13);

    // layer 3 (x13 30ch weighted | s13 100ch binary)
    k_spmm_dual<<<NB, 130>>>(30, 100, b30 + 60, b100);
    k_stats<<<128, 256, 2*130*sizeof(float)>>>(130, 240);
    k_apply<<<NB, 160>>>(3, gamma30, beta30, gamma100, beta100, W3030, Wp13);

    // assignment softmax, pooling
    k_s1softmax<<<NB, 128>>>(Wfc, bfc);
    k_adjs<<<NB, 100>>>();
    k_gemmTN<<<dim3(7, 7, Bg), dim3(16, 16)>>>(0);   // p1_adj = s^T (adj s)
    k_gemmTN<<<dim3(2, 7, Bg), dim3(16, 16)>>>(1);   // p1_x   = s^T x13
    k_A2<<<Bg, 128>>>();

    // stage 2
    k_conv2<<<dim3(Bg, 5), 256>>>(0, gamma30, beta30, W3030, b30);
    k_conv2<<<dim3(Bg, 5), 256>>>(1, gamma30, beta30, W3030, b30);
    k_conv2<<<dim3(Bg, 5), 256>>>(2, gamma30, beta30, W3030, b30);

    // readout
    k_max1<<<Bg, 96>>>();
    k_max2<<<Bg, 96>>>(gamma30, beta30);
    k_final<<<Bg, 192>>>(W1, b1, W2, b2, out);
}

// round 7
// speedup vs baseline: 1.3185x; 1.3185x over previous
#include <cuda_runtime.h>
#include <cstdint>

#define Bg 8
#define Nn 2048
#define NB (Bg*Nn)          // 16384 rows
#define MAXD 256            // max degree (mean ~102, 15 sigma margin)

// ---------------- device scratch ----------------
__device__ int2  g_edge[NB*MAXD];     // {col, float_as_int(val)}
__device__ int   g_cnt[NB];
__device__ float g_self[NB];
__device__ float g_dinvw[NB];
__device__ float g_dinvb[NB];

__device__ float g_T64[NB*64];        // layers 1/2 transformed feats, padded [w30,0,0 | b30,0,0]
__device__ float g_Tx [NB*32];        // layer-3 weighted feats (30 + 2 pad)
__device__ float g_Ts [NB*100];       // layer-3 binary feats (100)
__device__ float g_pre64 [NB*64];     // layers 1/2 pre-BN (padded 64)
__device__ float g_pre132[NB*132];    // layer-3 pre-BN (padded [32|100])

__device__ float g_x11[NB*30], g_x12[NB*30], g_x13[NB*30];
__device__ float g_s11[NB*30], g_s12[NB*30], g_s13[NB*100];
__device__ float g_sm [NB*100];
__device__ float g_adjs[NB*100];

__device__ float g_p1x  [Bg*100*30];
__device__ float g_p1adj[Bg*100*100];
__device__ float g_A2   [Bg*100*100];
__device__ float g_pre21[Bg*100*30], g_pre22[Bg*100*30], g_pre23[Bg*100*30];
__device__ float g_part1[Bg*16*90];
__device__ float g_x2out[Bg*90];

// stats: L1 @0 (64 sum + 64 sq), L2 @128 (128), L3 @256 (132+132=264),
//        S2a @520, S2b @580, S2c @640 (30+30 each)
#define STATS_TOTAL 700
__device__ float g_stats[STATS_TOTAL];

// ---------------- kernels ----------------
__global__ void k_zero_stats() {
    int i = blockIdx.x*blockDim.x + threadIdx.x;
    if (i < STATS_TOTAL) g_stats[i] = 0.f;
}

// Build edge list + degrees + fused layer-1 feature transform. grid (2048,8), block 256.
__global__ void k_build(const float* __restrict__ adj, const float* __restrict__ x,
                        const float* __restrict__ Win) {
    int i = blockIdx.x, b = blockIdx.y;
    int row = b*Nn + i;
    const float* arow = adj + (size_t)row * Nn;
    __shared__ int s_cnt;
    __shared__ float s_diag;
    __shared__ float red[256];
    __shared__ float s_dw, s_db;
    int tid = threadIdx.x;
    if (tid == 0) { s_cnt = 0; s_diag = 0.f; }
    __syncthreads();
    float wsum = 0.f;
    size_t base = (size_t)row * MAXD;
    for (int j = tid; j < Nn; j += 256) {
        float a = arow[j];
        if (j == i) s_diag = a;
        if (a != 0.f) {
            wsum += a;
            int pos = atomicAdd(&s_cnt, 1);
            if (pos < MAXD) g_edge[base+pos] = make_int2(j, __float_as_int(a));
        }
    }
    red[tid] = wsum;
    __syncthreads();
    for (int s = 128; s > 0; s >>= 1) { if (tid < s) red[tid] += red[tid+s]; __syncthreads(); }
    if (tid == 0) {
        int cnt = s_cnt;
        float d0 = (s_diag == 0.f) ? 1.f : 0.f;
        g_cnt[row]  = cnt < MAXD ? cnt : MAXD;
        g_self[row] = d0;
        float degw = red[0] + d0;
        float degb = (float)cnt + d0;
        float dw = degw > 0.f ? rsqrtf(degw) : 0.f;
        float db = degb > 0.f ? rsqrtf(degb) : 0.f;
        g_dinvw[row] = dw; g_dinvb[row] = db;
        s_dw = dw; s_db = db;
    }
    __syncthreads();
    if (tid < 64) {
        float x0 = x[row*3], x1 = x[row*3+1], x2 = x[row*3+2];
        int c = tid; float t = 0.f;
        if (c < 30) t = (x0*Win[c] + x1*Win[30+c] + x2*Win[60+c]) * s_dw;
        else if (c >= 32 && c < 62) {
            int c2 = c-32;
            t = (x0*Win[90+c2] + x1*Win[120+c2] + x2*Win[150+c2]) * s_db;
        }
        g_T64[(size_t)row*64 + c] = t;
    }
}

__device__ __forceinline__ float chb60(int c, const float* bx, const float* bs) {
    if (c < 30) return bx[c];
    if (c >= 32 && c < 62) return bs[c-32];
    return 0.f;
}

// layers 1/2 dual SpMM, warp-per-row, float4 lanes, fused stats. grid NB/8, block 256.
__global__ void k_spmm60(const float* __restrict__ biasX, const float* __restrict__ biasS,
                         int statOff) {
    __shared__ float sstat[8][128];
    int tid = threadIdx.x;
    int warp = tid >> 5, lane = tid & 31;
    int row = blockIdx.x*8 + warp;
    int bbase = row & ~(Nn-1);
    const float4* T4 = (const float4*)g_T64;
    int cl = lane & 15;
    float selfv = g_self[row];
    float4 t0 = T4[(size_t)row*16 + cl];
    float4 acc = make_float4(selfv*t0.x, selfv*t0.y, selfv*t0.z, selfv*t0.w);
    int cnt = g_cnt[row];
    const int2* ep = g_edge + (size_t)row*MAXD;
    #pragma unroll 4
    for (int k = 0; k < cnt; k++) {
        int2 e = ep[k];                         // warp-broadcast load
        float4 t = T4[(size_t)(bbase + e.x)*16 + cl];
        float w = (lane < 8) ? __int_as_float(e.y) : 1.0f;
        acc.x += w*t.x; acc.y += w*t.y; acc.z += w*t.z; acc.w += w*t.w;
    }
    if (lane < 16) {
        float dinv = (lane < 8) ? g_dinvw[row] : g_dinvb[row];
        int c0 = 4*lane;
        float4 bs = make_float4(chb60(c0,biasX,biasS), chb60(c0+1,biasX,biasS),
                                chb60(c0+2,biasX,biasS), chb60(c0+3,biasX,biasS));
        float4 o = make_float4(acc.x*dinv+bs.x, acc.y*dinv+bs.y,
                               acc.z*dinv+bs.z, acc.w*dinv+bs.w);
        ((float4*)g_pre64)[(size_t)row*16 + lane] = o;
        sstat[warp][c0+0]=o.x; sstat[warp][c0+1]=o.y; sstat[warp][c0+2]=o.z; sstat[warp][c0+3]=o.w;
        sstat[warp][64+c0+0]=o.x*o.x; sstat[warp][64+c0+1]=o.y*o.y;
        sstat[warp][64+c0+2]=o.z*o.z; sstat[warp][64+c0+3]=o.w*o.w;
    }
    __syncthreads();
    for (int i = tid; i < 128; i += 256) {
        float s = 0.f;
        #pragma unroll
        for (int wq = 0; wq < 8; wq++) s += sstat[wq][i];
        atomicAdd(&g_stats[statOff + i], s);
    }
}

// layer-3 dual SpMM: 2 warps/row (weighted 32-pad, binary 100). grid NB/4, block 256.
__global__ void k_spmm130(const float* __restrict__ biasX, const float* __restrict__ biasS) {
    __shared__ float sstat[264];
    int tid = threadIdx.x;
    for (int i = tid; i < 264; i += 256) sstat[i] = 0.f;
    __syncthreads();
    int warp = tid >> 5, lane = tid & 31;
    int row = blockIdx.x*4 + (warp >> 1);
    int role = warp & 1;
    int bbase = row & ~(Nn-1);
    int cnt = g_cnt[row];
    float selfv = g_self[row];
    const int2* ep = g_edge + (size_t)row*MAXD;
    if (role == 0) {
        const float4* T4 = (const float4*)g_Tx;
        int cl = lane & 7;
        float4 t0 = T4[(size_t)row*8 + cl];
        float4 acc = make_float4(selfv*t0.x, selfv*t0.y, selfv*t0.z, selfv*t0.w);
        #pragma unroll 4
        for (int k = 0; k < cnt; k++) {
            int2 e = ep[k];
            float4 t = T4[(size_t)(bbase + e.x)*8 + cl];
            float w = __int_as_float(e.y);
            acc.x += w*t.x; acc.y += w*t.y; acc.z += w*t.z; acc.w += w*t.w;
        }
        if (lane < 8) {
            float dinv = g_dinvw[row];
            int c0 = 4*lane;
            float4 bs = make_float4(c0<30?biasX[c0]:0.f, c0+1<30?biasX[c0+1]:0.f,
                                    c0+2<30?biasX[c0+2]:0.f, c0+3<30?biasX[c0+3]:0.f);
            float4 o = make_float4(acc.x*dinv+bs.x, acc.y*dinv+bs.y,
                                   acc.z*dinv+bs.z, acc.w*dinv+bs.w);
            ((float4*)g_pre132)[(size_t)row*33 + lane] = o;
            atomicAdd(&sstat[c0+0], o.x); atomicAdd(&sstat[c0+1], o.y);
            atomicAdd(&sstat[c0+2], o.z); atomicAdd(&sstat[c0+3], o.w);
            atomicAdd(&sstat[132+c0+0], o.x*o.x); atomicAdd(&sstat[132+c0+1], o.y*o.y);
            atomicAdd(&sstat[132+c0+2], o.z*o.z); atomicAdd(&sstat[132+c0+3], o.w*o.w);
        }
    } else {
        const float4* S4 = (const float4*)g_Ts;
        int cl = lane < 24 ? lane : 24;
        float4 t0 = S4[(size_t)row*25 + cl];
        float4 acc = make_float4(selfv*t0.x, selfv*t0.y, selfv*t0.z, selfv*t0.w);
        #pragma unroll 4
        for (int k = 0; k < cnt; k++) {
            int2 e = ep[k];
            float4 t = S4[(size_t)(bbase + e.x)*25 + cl];
            acc.x += t.x; acc.y += t.y; acc.z += t.z; acc.w += t.w;
        }
        if (lane < 25) {
            float dinv = g_dinvb[row];
            float4 bs = ((const float4*)biasS)[lane];
            float4 o = make_float4(acc.x*dinv+bs.x, acc.y*dinv+bs.y,
                                   acc.z*dinv+bs.z, acc.w*dinv+bs.w);
            ((float4*)g_pre132)[(size_t)row*33 + 8 + lane] = o;
            int c0 = 32 + 4*lane;
            atomicAdd(&sstat[c0+0], o.x); atomicAdd(&sstat[c0+1], o.y);
            atomicAdd(&sstat[c0+2], o.z); atomicAdd(&sstat[c0+3], o.w);
            atomicAdd(&sstat[132+c0+0], o.x*o.x); atomicAdd(&sstat[132+c0+1], o.y*o.y);
            atomicAdd(&sstat[132+c0+2], o.z*o.z); atomicAdd(&sstat[132+c0+3], o.w*o.w);
        }
    }
    __syncthreads();
    for (int i = tid; i < 264; i += 256) atomicAdd(&g_stats[256 + i], sstat[i]);
}

// adj @ s, warp-per-row float4. grid NB/8, block 256.
__global__ void k_adjs() {
    int tid = threadIdx.x;
    int warp = tid >> 5, lane = tid & 31;
    int row = blockIdx.x*8 + warp;
    int bbase = row & ~(Nn-1);
    const float4* S4 = (const float4*)g_sm;
    int cl = lane < 24 ? lane : 24;
    float4 acc = make_float4(0.f, 0.f, 0.f, 0.f);
    int cnt = g_cnt[row];
    const int2* ep = g_edge + (size_t)row*MAXD;
    #pragma unroll 4
    for (int k = 0; k < cnt; k++) {
        int2 e = ep[k];
        float4 t = S4[(size_t)(bbase + e.x)*25 + cl];
        float w = __int_as_float(e.y);
        acc.x += w*t.x; acc.y += w*t.y; acc.z += w*t.z; acc.w += w*t.w;
    }
    if (lane < 25) ((float4*)g_adjs)[(size_t)row*25 + lane] = acc;
}

// apply BN + store branch outputs + compute next layer's T. grid NB, block 160.
__global__ void k_apply(int layer,
                        const float* __restrict__ gamma30, const float* __restrict__ beta30,
                        const float* __restrict__ gamma100, const float* __restrict__ beta100,
                        const float* __restrict__ W3030, const float* __restrict__ Wp13)
{
    int row = blockIdx.x;
    int tid = threadIdx.x;
    __shared__ float sh[132];
    const float invM = 1.0f / (float)NB;

    int Cin, off, stride;
    const float *gX, *bX, *gS, *bS, *pre;
    float *outX, *outS;
    if (layer == 1) {
        Cin=60; off=0;   stride=64;  gX=gamma30;    bX=beta30;    gS=gamma30+90;  bS=beta30+90;
        outX=g_x11; outS=g_s11; pre=g_pre64;
    } else if (layer == 2) {
        Cin=60; off=128; stride=64;  gX=gamma30+30; bX=beta30+30; gS=gamma30+120; bS=beta30+120;
        outX=g_x12; outS=g_s12; pre=g_pre64;
    } else {
        Cin=130; off=256; stride=132; gX=gamma30+60; bX=beta30+60; gS=gamma100;   bS=beta100;
        outX=g_x13; outS=g_s13; pre=g_pre132;
    }
    int CxIn = 30, CsIn = Cin - 30;
    if (tid < Cin) {
        int pc = (tid < 30) ? tid : tid + 2;    // padded index
        float sum = g_stats[off + pc], sq = g_stats[off + stride + pc];
        float mean = sum * invM;
        float var  = fmaxf(sq * invM - mean*mean, 0.f);
        float g, bb;
        if (tid < CxIn) { g = gX[tid]; bb = bX[tid]; }
        else            { g = gS[tid-CxIn]; bb = bS[tid-CxIn]; }
        float v = (pre[(size_t)row*stride + pc] - mean) * rsqrtf(var + 1e-5f) * g + bb;
        sh[tid] = v;
        if (tid < CxIn) outX[(size_t)row*CxIn + tid] = v;
        else            outS[(size_t)row*CsIn + tid - CxIn] = v;
    }
    if (layer == 3) return;
    __syncthreads();
    float dw = g_dinvw[row], db = g_dinvb[row];
    if (layer == 1) {
        const float* Wx = W3030;          // conv12
        const float* Ws = W3030 + 1800;   // pool_conv12
        if (tid < 64) {
            int c = tid; float t = 0.f;
            if (c < 30) {
                #pragma unroll 6
                for (int k = 0; k < 30; k++) t += sh[k]*Wx[k*30 + c];
                t *= dw;
            } else if (c >= 32 && c < 62) {
                int c2 = c - 32;
                #pragma unroll 6
                for (int k = 0; k < 30; k++) t += sh[30+k]*Ws[k*30 + c2];
                t *= db;
            }
            g_T64[(size_t)row*64 + c] = t;
        }
    } else {
        const float* Wx = W3030 + 900;    // conv13
        if (tid < 32) {
            int c = tid; float t = 0.f;
            if (c < 30) {
                #pragma unroll 6
                for (int k = 0; k < 30; k++) t += sh[k]*Wx[k*30 + c];
                t *= dw;
            }
            g_Tx[(size_t)row*32 + c] = t;
        } else if (tid < 132) {
            int c2 = tid - 32; float t = 0.f;
            #pragma unroll 6
            for (int k = 0; k < 30; k++) t += sh[30+k]*Wp13[k*100 + c2];
            g_Ts[(size_t)row*100 + c2] = t * db;
        }
    }
}

// s1 = [s11|s12|s13] @ Wfc + bfc, softmax. grid NB, block 64, float2 per thread.
__global__ void k_s1softmax(const float* __restrict__ Wfc, const float* __restrict__ bfc) {
    int row = blockIdx.x;
    __shared__ float sin[160];
    __shared__ float red[64];
    int tid = threadIdx.x;
    if (tid < 30) { sin[tid] = g_s11[row*30+tid]; sin[30+tid] = g_s12[row*30+tid]; }
    for (int i = tid; i < 100; i += 64) sin[60+i] = g_s13[(size_t)row*100+i];
    __syncthreads();
    float2 z = make_float2(-1e30f, -1e30f);
    if (tid < 50) {
        const float2* W2p = (const float2*)Wfc;
        float2 acc = ((const float2*)bfc)[tid];
        #pragma unroll 8
        for (int k = 0; k < 160; k++) {
            float s = sin[k];
            float2 w = W2p[k*50 + tid];
            acc.x += s*w.x; acc.y += s*w.y;
        }
        z = acc;
    }
    red[tid] = fmaxf(z.x, z.y);
    __syncthreads();
    for (int s = 32; s > 0; s >>= 1) { if (tid < s) red[tid] = fmaxf(red[tid], red[tid+s]); __syncthreads(); }
    float mx = red[0];
    __syncthreads();
    float ex = 0.f, ey = 0.f;
    if (tid < 50) { ex = expf(z.x - mx); ey = expf(z.y - mx); }
    red[tid] = ex + ey;
    __syncthreads();
    for (int s = 32; s > 0; s >>= 1) { if (tid < s) red[tid] += red[tid+s]; __syncthreads(); }
    float inv = 1.0f / red[0];
    if (tid < 50) ((float2*)g_sm)[(size_t)row*50 + tid] = make_float2(ex*inv, ey*inv);
}

// C[b,m,l] = sum_n s[b,n,m] * B[b,n,l]
__global__ void k_gemmTN(int mode) {
    int CB = mode == 0 ? 100 : 30;
    const float* Bm = mode == 0 ? g_adjs : g_x13;
    float* C = mode == 0 ? g_p1adj : g_p1x;
    int b = blockIdx.z;
    int m0 = blockIdx.y*16, l0 = blockIdx.x*16;
    int tx = threadIdx.x, ty = threadIdx.y;
    __shared__ float As[16][17], Bs[16][17];
    const float* Ab = g_sm + (size_t)b*Nn*100;
    const float* Bb = Bm  + (size_t)b*Nn*CB;
    float acc = 0.f;
    for (int n0 = 0; n0 < Nn; n0 += 16) {
        int am = m0 + tx;
        As[ty][tx] = (am < 100) ? Ab[(n0+ty)*100 + am] : 0.f;
        int bl = l0 + tx;
        Bs[ty][tx] = (bl < CB) ? Bb[(n0+ty)*CB + bl] : 0.f;
        __syncthreads();
        #pragma unroll
        for (int i = 0; i < 16; i++) acc += As[i][ty]*Bs[i][tx];
        __syncthreads();
    }
    int m = m0+ty, l = l0+tx;
    if (m < 100 && l < CB) C[((size_t)b*100 + m)*CB + l] = acc;
}

__global__ void k_A2() {
    int b = blockIdx.x;
    const float* p = g_p1adj + b*10000;
    __shared__ float dinv[100], sflag[100];
    int tid = threadIdx.x;
    if (tid < 100) {
        float s = 0.f;
        float diag = p[tid*100+tid];
        for (int j = 0; j < 100; j++) s += p[tid*100+j];
        float d0 = (diag == 0.f) ? 1.f : 0.f;
        float deg = s + d0;
        dinv[tid] = deg > 0.f ? rsqrtf(deg) : 0.f;
        sflag[tid] = d0;
    }
    __syncthreads();
    for (int idx = tid; idx < 10000; idx += blockDim.x) {
        int i = idx/100, j = idx%100;
        float v = p[idx] + ((i == j) ? sflag[i] : 0.f);
        g_A2[b*10000+idx] = dinv[i]*v*dinv[j];
    }
}

// stage-2 conv with fused BN-in and stats-out. grid (8,5), block 256.
__global__ void k_conv2(int mode,
                        const float* __restrict__ gamma30, const float* __restrict__ beta30,
                        const float* __restrict__ W3030, const float* __restrict__ b30)
{
    const float *in, *W, *bias, *gR = nullptr, *bR = nullptr;
    float* outPre; int useBN, offIn = 0, offOut;
    if (mode == 0) { in=g_p1x;  useBN=0;            outPre=g_pre21; offOut=520; W=W3030+2700; bias=b30+150; }
    else if (mode == 1) { in=g_pre21; useBN=1; offIn=520; gR=gamma30+150; bR=beta30+150;
                          outPre=g_pre22; offOut=580; W=W3030+3600; bias=b30+180; }
    else { in=g_pre22; useBN=1; offIn=580; gR=gamma30+180; bR=beta30+180;
           outPre=g_pre23; offOut=640; W=W3030+4500; bias=b30+210; }
    int b = blockIdx.x, chunk = blockIdx.y;
    __shared__ float shin[3000], shtmp[3000];
    __shared__ float scale[30], shift[30], ss[30], sq[30];
    int tid = threadIdx.x;
    if (tid < 30) {
        ss[tid] = 0.f; sq[tid] = 0.f;
        if (useBN) {
            float sum = g_stats[offIn+tid], q = g_stats[offIn+30+tid];
            float m = sum*(1.f/800.f);
            float v = fmaxf(q*(1.f/800.f) - m*m, 0.f);
            float sc = rsqrtf(v+1e-5f)*gR[tid];
            scale[tid] = sc; shift[tid] = bR[tid] - m*sc;
        } else { scale[tid] = 1.f; shift[tid] = 0.f; }
    }
    __syncthreads();
    for (int idx = tid; idx < 3000; idx += 256) {
        int c = idx % 30;
        shin[idx] = in[b*3000+idx]*scale[c] + shift[c];
    }
    __syncthreads();
    for (int idx = tid; idx < 3000; idx += 256) {
        int j = idx/30, c = idx%30;
        float t = 0.f;
        #pragma unroll 6
        for (int k = 0; k < 30; k++) t += shin[j*30+k]*W[k*30+c];
        shtmp[idx] = t;
    }
    __syncthreads();
    const float* A2b = g_A2 + b*10000;
    for (int idx = tid; idx < 600; idx += 256) {
        int il = idx/30, c = idx%30;
        int i = chunk*20 + il;
        float acc = bias[c];
        const float* arow = A2b + i*100;
        #pragma unroll 4
        for (int j = 0; j < 100; j++) acc += arow[j]*shtmp[j*30+c];
        outPre[b*3000 + i*30 + c] = acc;
        atomicAdd(&ss[c], acc);
        atomicAdd(&sq[c], acc*acc);
    }
    __syncthreads();
    if (tid < 30) {
        atomicAdd(&g_stats[offOut+tid], ss[tid]);
        atomicAdd(&g_stats[offOut+30+tid], sq[tid]);
    }
}

// stage-1 max pool partials. grid (8,16), block 96.
__global__ void k_max1() {
    int b = blockIdx.x, ch = blockIdx.y, c = threadIdx.x;
    if (c >= 90) return;
    int which = c/30, cc = c%30;
    const float* buf = which == 0 ? g_x11 : which == 1 ? g_x12 : g_x13;
    const float* p = buf + ((size_t)b*Nn + ch*128)*30 + cc;
    float m = -3.4e38f;
    #pragma unroll 8
    for (int n = 0; n < 128; n++) m = fmaxf(m, p[n*30]);
    g_part1[(b*16+ch)*90 + c] = m;
}

// stage-2 max pool with lazy BN. grid 8, block 96.
__global__ void k_max2(const float* __restrict__ gamma30, const float* __restrict__ beta30) {
    int b = blockIdx.x, c = threadIdx.x;
    if (c >= 90) return;
    int which = c/30, cc = c%30;
    const float* buf = which == 0 ? g_pre21 : which == 1 ? g_pre22 : g_pre23;
    int off = 520 + which*60;
    float sum = g_stats[off+cc], q = g_stats[off+30+cc];
    float mn = sum*(1.f/800.f);
    float var = fmaxf(q*(1.f/800.f) - mn*mn, 0.f);
    float g  = gamma30[(5+which)*30+cc];
    float be = beta30 [(5+which)*30+cc];
    float sc = rsqrtf(var+1e-5f)*g;
    float sh = be - mn*sc;
    const float* p = buf + b*3000 + cc;
    float m = -3.4e38f;
    #pragma unroll 4
    for (int k = 0; k < 100; k++) m = fmaxf(m, p[k*30]*sc + sh);
    g_x2out[b*90+c] = m;
}

// final MLP, reduces stage-1 partial maxima. grid 8, block 192.
__global__ void k_final(const float* __restrict__ W1, const float* __restrict__ b1,
                        const float* __restrict__ W2, const float* __restrict__ b2,
                        float* __restrict__ out)
{
    int b = blockIdx.x, tid = threadIdx.x;
    __shared__ float sh[180];
    __shared__ float hh[50];
    if (tid < 90) {
        float m = -3.4e38f;
        #pragma unroll
        for (int q = 0; q < 16; q++) m = fmaxf(m, g_part1[(b*16+q)*90 + tid]);
        sh[tid] = m;
    } else if (tid < 180) sh[tid] = g_x2out[b*90 + tid - 90];
    __syncthreads();
    if (tid < 50) {
        float acc = b1[tid];
        #pragma unroll 4
        for (int k = 0; k < 180; k++) acc += sh[k]*W1[k*50+tid];
        hh[tid] = fmaxf(acc, 0.f);
    }
    __syncthreads();
    if (tid < 6) {
        float acc = b2[tid];
        #pragma unroll
        for (int k = 0; k < 50; k++) acc += hh[k]*W2[k*6+tid];
        out[b*6+tid] = acc;
    }
}

// ---------------- host launch ----------------
extern "C" void kernel_launch(void* const* d_in, const int* in_sizes, int n_in,
                              void* d_out, int out_size) {
    const float* x        = (const float*)d_in[0];
    const float* adj      = (const float*)d_in[1];
    const float* W_in     = (const float*)d_in[2];
    const float* W3030    = (const float*)d_in[3];
    const float* Wp13     = (const float*)d_in[4];
    const float* b30      = (const float*)d_in[5];
    const float* b100     = (const float*)d_in[6];
    const float* Wfc      = (const float*)d_in[7];
    const float* bfc      = (const float*)d_in[8];
    const float* W1       = (const float*)d_in[9];
    const float* b1       = (const float*)d_in[10];
    const float* W2       = (const float*)d_in[11];
    const float* b2       = (const float*)d_in[12];
    const float* gamma30  = (const float*)d_in[13];
    const float* beta30   = (const float*)d_in[14];
    const float* gamma100 = (const float*)d_in[15];
    const float* beta100  = (const float*)d_in[16];
    float* out = (float*)d_out;

    k_zero_stats<<<3, 256>>>();
    k_build<<<dim3(Nn, Bg), 256>>>(adj, x, W_in);

    // layer 1
    k_spmm60<<<NB/8, 256>>>(b30 + 0, b30 + 90, 0);
    k_apply<<<NB, 160>>>(1, gamma30, beta30, gamma100, beta100, W3030, Wp13);
    // layer 2
    k_spmm60<<<NB/8, 256>>>(b30 + 30, b30 + 120, 128);
    k_apply<<<NB, 160>>>(2, gamma30, beta30, gamma100, beta100, W3030, Wp13);
    // layer 3
    k_spmm130<<<NB/4, 256>>>(b30 + 60, b100);
    k_apply<<<NB, 160>>>(3, gamma30, beta30, gamma100, beta100, W3030, Wp13);

    // assignment softmax, pooling
    k_s1softmax<<<NB, 64>>>(Wfc, bfc);
    k_adjs<<<NB/8, 256>>>();
    k_gemmTN<<<dim3(7, 7, Bg), dim3(16, 16)>>>(0);   // p1_adj
    k_gemmTN<<<dim3(2, 7, Bg), dim3(16, 16)>>>(1);   // p1_x
    k_A2<<<Bg, 128>>>();

    // stage 2
    k_conv2<<<dim3(Bg, 5), 256>>>(0, gamma30, beta30, W3030, b30);
    k_conv2<<<dim3(Bg, 5), 256>>>(1, gamma30, beta30, W3030, b30);
    k_conv2<<<dim3(Bg, 5), 256>>>(2, gamma30, beta30, W3030, b30);

    // readout
    k_max1<<<dim3(Bg, 16), 96>>>();
    k_max2<<<Bg, 96>>>(gamma30, beta30);
    k_final<<<Bg, 192>>>(W1, b1, W2, b2, out);
}

// round 12
// speedup vs baseline: 1.4505x; 1.1001x over previous
#include <cuda_runtime.h>
#include <cstdint>

#define Bg 8
#define Nn 2048
#define NB (Bg*Nn)          // 16384 rows
#define MAXD 256            // max degree (mean ~102)

// ---------------- device scratch ----------------
__device__ int2  g_edge[NB*MAXD];     // {col, float_as_int(val)}
__device__ int   g_cnt[NB];
__device__ float g_self[NB];
__device__ float g_dinvw[NB];
__device__ float g_dinvb[NB];

__device__ float g_T64[NB*64];        // layers 1/2 transformed feats, padded [w30,p2 | b30,p2]
__device__ float g_Tx [NB*32];        // layer-3 weighted feats (30 + 2 pad)
__device__ float g_Ts [NB*100];       // layer-3 binary feats (100)
__device__ float g_pre64 [NB*64];     // layers 1/2 pre-BN (padded 64)
__device__ float g_pre132[NB*132];    // layer-3 pre-BN (padded [32|100])

__device__ float g_x11[NB*30], g_x12[NB*30], g_x13[NB*30];
__device__ float g_s11[NB*30], g_s12[NB*30], g_s13[NB*100];
__device__ float g_sm [NB*100];
__device__ float g_adjs[NB*100];

__device__ float g_p1x  [Bg*100*30];
__device__ float g_p1adj[Bg*100*100];
__device__ float g_A2   [Bg*100*100];
__device__ float g_pre21[Bg*100*30], g_pre22[Bg*100*30], g_pre23[Bg*100*30];
__device__ float g_part1[Bg*16*90];

// stats: L1 @0 (64 sum + 64 sq), L2 @128, L3 @256 (132+132),
//        S2a @520, S2b @580, S2c @640 (30+30 each)
#define STATS_TOTAL 700
__device__ float g_stats[STATS_TOTAL];

// Build edge list + degrees + fused layer-1 transform + stats zeroing. grid (2048,8), block 256.
__global__ void k_build(const float* __restrict__ adj, const float* __restrict__ x,
                        const float* __restrict__ Win) {
    int i = blockIdx.x, b = blockIdx.y;
    int tid = threadIdx.x;
    if (i == 0 && b == 0) {
        for (int q = tid; q < STATS_TOTAL; q += 256) g_stats[q] = 0.f;
    }
    int row = b*Nn + i;
    const float* arow = adj + (size_t)row * Nn;
    __shared__ int s_cnt;
    __shared__ float s_diag;
    __shared__ float red[256];
    __shared__ float s_dw, s_db;
    if (tid == 0) { s_cnt = 0; s_diag = 0.f; }
    __syncthreads();
    float wsum = 0.f;
    size_t base = (size_t)row * MAXD;
    for (int j = tid; j < Nn; j += 256) {
        float a = arow[j];
        if (j == i) s_diag = a;
        if (a != 0.f) {
            wsum += a;
            int pos = atomicAdd(&s_cnt, 1);
            if (pos < MAXD) g_edge[base+pos] = make_int2(j, __float_as_int(a));
        }
    }
    red[tid] = wsum;
    __syncthreads();
    for (int s = 128; s > 0; s >>= 1) { if (tid < s) red[tid] += red[tid+s]; __syncthreads(); }
    if (tid == 0) {
        int cnt = s_cnt;
        float d0 = (s_diag == 0.f) ? 1.f : 0.f;
        g_cnt[row]  = cnt < MAXD ? cnt : MAXD;
        g_self[row] = d0;
        float degw = red[0] + d0;
        float degb = (float)cnt + d0;
        float dw = degw > 0.f ? rsqrtf(degw) : 0.f;
        float db = degb > 0.f ? rsqrtf(degb) : 0.f;
        g_dinvw[row] = dw; g_dinvb[row] = db;
        s_dw = dw; s_db = db;
    }
    __syncthreads();
    if (tid < 64) {
        float x0 = x[row*3], x1 = x[row*3+1], x2 = x[row*3+2];
        int c = tid; float t = 0.f;
        if (c < 30) t = (x0*Win[c] + x1*Win[30+c] + x2*Win[60+c]) * s_dw;
        else if (c >= 32 && c < 62) {
            int c2 = c-32;
            t = (x0*Win[90+c2] + x1*Win[120+c2] + x2*Win[150+c2]) * s_db;
        }
        g_T64[(size_t)row*64 + c] = t;
    }
}

__device__ __forceinline__ float chb60(int c, const float* bx, const float* bs) {
    if (c < 30) return bx[c];
    if (c >= 32 && c < 62) return bs[c-32];
    return 0.f;
}

// layers 1/2 dual SpMM: warp-per-row, 2 edges/iter (half-warps), fused stats. grid NB/8, block 256.
__global__ void k_spmm60(const float* __restrict__ biasX, const float* __restrict__ biasS,
                         int statOff) {
    __shared__ float sstat[8][128];
    int tid = threadIdx.x;
    int warp = tid >> 5, lane = tid & 31;
    int row = blockIdx.x*8 + warp;
    int bbase = row & ~(Nn-1);
    const float4* T4 = (const float4*)g_T64;
    int hf = lane >> 4;            // which edge of the pair
    int cl = lane & 15;            // float4 channel group
    float selfv = (hf == 0) ? g_self[row] : 0.f;
    float4 t0 = T4[(size_t)row*16 + cl];
    float4 acc = make_float4(selfv*t0.x, selfv*t0.y, selfv*t0.z, selfv*t0.w);
    int cnt = g_cnt[row];
    const int2* ep = g_edge + (size_t)row*MAXD;
    for (int k = 0; k < cnt; k += 2) {
        int kk = k + hf;
        int2 e = ep[kk < cnt ? kk : (cnt-1)];
        float4 t = T4[(size_t)(bbase + e.x)*16 + cl];
        float w = (kk < cnt) ? ((cl < 8) ? __int_as_float(e.y) : 1.0f) : 0.f;
        acc.x += w*t.x; acc.y += w*t.y; acc.z += w*t.z; acc.w += w*t.w;
    }
    acc.x += __shfl_xor_sync(0xffffffffu, acc.x, 16);
    acc.y += __shfl_xor_sync(0xffffffffu, acc.y, 16);
    acc.z += __shfl_xor_sync(0xffffffffu, acc.z, 16);
    acc.w += __shfl_xor_sync(0xffffffffu, acc.w, 16);
    if (lane < 16) {
        float dinv = (lane < 8) ? g_dinvw[row] : g_dinvb[row];
        int c0 = 4*lane;
        float4 bs = make_float4(chb60(c0,biasX,biasS), chb60(c0+1,biasX,biasS),
                                chb60(c0+2,biasX,biasS), chb60(c0+3,biasX,biasS));
        float4 o = make_float4(acc.x*dinv+bs.x, acc.y*dinv+bs.y,
                               acc.z*dinv+bs.z, acc.w*dinv+bs.w);
        ((float4*)g_pre64)[(size_t)row*16 + lane] = o;
        sstat[warp][c0+0]=o.x; sstat[warp][c0+1]=o.y; sstat[warp][c0+2]=o.z; sstat[warp][c0+3]=o.w;
        sstat[warp][64+c0+0]=o.x*o.x; sstat[warp][64+c0+1]=o.y*o.y;
        sstat[warp][64+c0+2]=o.z*o.z; sstat[warp][64+c0+3]=o.w*o.w;
    }
    __syncthreads();
    for (int i = tid; i < 128; i += 256) {
        float s = 0.f;
        #pragma unroll
        for (int wq = 0; wq < 8; wq++) s += sstat[wq][i];
        atomicAdd(&g_stats[statOff + i], s);
    }
}

// layer-3 dual SpMM: 2 warps/row. role0 weighted 32ch, 4 edges/iter; role1 binary 100ch.
// grid NB/4, block 256.
__global__ void k_spmm130(const float* __restrict__ biasX, const float* __restrict__ biasS) {
    __shared__ float sstat[264];
    int tid = threadIdx.x;
    for (int i = tid; i < 264; i += 256) sstat[i] = 0.f;
    __syncthreads();
    int warp = tid >> 5, lane = tid & 31;
    int row = blockIdx.x*4 + (warp >> 1);
    int role = warp & 1;
    int bbase = row & ~(Nn-1);
    int cnt = g_cnt[row];
    const int2* ep = g_edge + (size_t)row*MAXD;
    if (role == 0) {
        const float4* T4 = (const float4*)g_Tx;
        int qt = lane >> 3;        // which edge of the quad
        int cl = lane & 7;
        float selfv = (qt == 0) ? g_self[row] : 0.f;
        float4 t0 = T4[(size_t)row*8 + cl];
        float4 acc = make_float4(selfv*t0.x, selfv*t0.y, selfv*t0.z, selfv*t0.w);
        for (int k = 0; k < cnt; k += 4) {
            int kk = k + qt;
            int2 e = ep[kk < cnt ? kk : (cnt-1)];
            float4 t = T4[(size_t)(bbase + e.x)*8 + cl];
            float w = (kk < cnt) ? __int_as_float(e.y) : 0.f;
            acc.x += w*t.x; acc.y += w*t.y; acc.z += w*t.z; acc.w += w*t.w;
        }
        acc.x += __shfl_xor_sync(0xffffffffu, acc.x, 8);
        acc.y += __shfl_xor_sync(0xffffffffu, acc.y, 8);
        acc.z += __shfl_xor_sync(0xffffffffu, acc.z, 8);
        acc.w += __shfl_xor_sync(0xffffffffu, acc.w, 8);
        acc.x += __shfl_xor_sync(0xffffffffu, acc.x, 16);
        acc.y += __shfl_xor_sync(0xffffffffu, acc.y, 16);
        acc.z += __shfl_xor_sync(0xffffffffu, acc.z, 16);
        acc.w += __shfl_xor_sync(0xffffffffu, acc.w, 16);
        if (lane < 8) {
            float dinv = g_dinvw[row];
            int c0 = 4*lane;
            float4 bs = make_float4(c0<30?biasX[c0]:0.f, c0+1<30?biasX[c0+1]:0.f,
                                    c0+2<30?biasX[c0+2]:0.f, c0+3<30?biasX[c0+3]:0.f);
            float4 o = make_float4(acc.x*dinv+bs.x, acc.y*dinv+bs.y,
                                   acc.z*dinv+bs.z, acc.w*dinv+bs.w);
            ((float4*)g_pre132)[(size_t)row*33 + lane] = o;
            atomicAdd(&sstat[c0+0], o.x); atomicAdd(&sstat[c0+1], o.y);
            atomicAdd(&sstat[c0+2], o.z); atomicAdd(&sstat[c0+3], o.w);
            atomicAdd(&sstat[132+c0+0], o.x*o.x); atomicAdd(&sstat[132+c0+1], o.y*o.y);
            atomicAdd(&sstat[132+c0+2], o.z*o.z); atomicAdd(&sstat[132+c0+3], o.w*o.w);
        }
    } else {
        const float4* S4 = (const float4*)g_Ts;
        int cl = lane < 24 ? lane : 24;
        float selfv = g_self[row];
        float4 t0 = S4[(size_t)row*25 + cl];
        float4 acc = make_float4(selfv*t0.x, selfv*t0.y, selfv*t0.z, selfv*t0.w);
        #pragma unroll 4
        for (int k = 0; k < cnt; k++) {
            int2 e = ep[k];
            float4 t = S4[(size_t)(bbase + e.x)*25 + cl];
            acc.x += t.x; acc.y += t.y; acc.z += t.z; acc.w += t.w;
        }
        if (lane < 25) {
            float dinv = g_dinvb[row];
            float4 bs = ((const float4*)biasS)[lane];
            float4 o = make_float4(acc.x*dinv+bs.x, acc.y*dinv+bs.y,
                                   acc.z*dinv+bs.z, acc.w*dinv+bs.w);
            ((float4*)g_pre132)[(size_t)row*33 + 8 + lane] = o;
            int c0 = 32 + 4*lane;
            atomicAdd(&sstat[c0+0], o.x); atomicAdd(&sstat[c0+1], o.y);
            atomicAdd(&sstat[c0+2], o.z); atomicAdd(&sstat[c0+3], o.w);
            atomicAdd(&sstat[132+c0+0], o.x*o.x); atomicAdd(&sstat[132+c0+1], o.y*o.y);
            atomicAdd(&sstat[132+c0+2], o.z*o.z); atomicAdd(&sstat[132+c0+3], o.w*o.w);
        }
    }
    __syncthreads();
    for (int i = tid; i < 264; i += 256) atomicAdd(&g_stats[256 + i], sstat[i]);
}

// adj @ s, warp-per-row float4. grid NB/8, block 256.
__global__ void k_adjs() {
    int tid = threadIdx.x;
    int warp = tid >> 5, lane = tid & 31;
    int row = blockIdx.x*8 + warp;
    int bbase = row & ~(Nn-1);
    const float4* S4 = (const float4*)g_sm;
    int cl = lane < 24 ? lane : 24;
    float4 acc = make_float4(0.f, 0.f, 0.f, 0.f);
    int cnt = g_cnt[row];
    const int2* ep = g_edge + (size_t)row*MAXD;
    #pragma unroll 4
    for (int k = 0; k < cnt; k++) {
        int2 e = ep[k];
        float4 t = S4[(size_t)(bbase + e.x)*25 + cl];
        float w = __int_as_float(e.y);
        acc.x += w*t.x; acc.y += w*t.y; acc.z += w*t.z; acc.w += w*t.w;
    }
    if (lane < 25) ((float4*)g_adjs)[(size_t)row*25 + lane] = acc;
}

// layers 1/2: warp-per-row BN-apply + next-layer transform via shuffles. grid NB/8, block 256.
__global__ void k_apply12(int layer,
                          const float* __restrict__ gamma30, const float* __restrict__ beta30,
                          const float* __restrict__ W3030, const float* __restrict__ Wp13)
{
    int tid = threadIdx.x;
    int warp = tid >> 5, lane = tid & 31;
    int row = blockIdx.x*8 + warp;
    const float invM = 1.0f / (float)NB;
    int off; const float *gX, *bX, *gS, *bS; float *outX, *outS;
    if (layer == 1) {
        off=0;   gX=gamma30;    bX=beta30;    gS=gamma30+90;  bS=beta30+90;
        outX=g_x11; outS=g_s11;
    } else {
        off=128; gX=gamma30+30; bX=beta30+30; gS=gamma30+120; bS=beta30+120;
        outX=g_x12; outS=g_s12;
    }
    int c = lane < 30 ? lane : 29;   // clamp for shuffle-safety
    // BN x-branch
    float sumx = g_stats[off + c], sqx = g_stats[off + 64 + c];
    float mx = sumx * invM;
    float vrx = fmaxf(sqx*invM - mx*mx, 0.f);
    float vx = (g_pre64[(size_t)row*64 + c] - mx) * rsqrtf(vrx + 1e-5f) * gX[c] + bX[c];
    // BN s-branch
    float sums = g_stats[off + 32 + c], sqs = g_stats[off + 64 + 32 + c];
    float ms = sums * invM;
    float vrs = fmaxf(sqs*invM - ms*ms, 0.f);
    float vs = (g_pre64[(size_t)row*64 + 32 + c] - ms) * rsqrtf(vrs + 1e-5f) * gS[c] + bS[c];
    if (lane < 30) {
        outX[(size_t)row*30 + lane] = vx;
        outS[(size_t)row*30 + lane] = vs;
    }
    float dw = g_dinvw[row], db = g_dinvb[row];
    if (layer == 1) {
        const float* Wx = W3030;          // conv12
        const float* Ws = W3030 + 1800;   // pool_conv12
        float tx = 0.f, ts = 0.f;
        #pragma unroll 6
        for (int k = 0; k < 30; k++) {
            float xk = __shfl_sync(0xffffffffu, vx, k);
            float sk = __shfl_sync(0xffffffffu, vs, k);
            tx += xk * Wx[k*30 + c];
            ts += sk * Ws[k*30 + c];
        }
        if (lane < 30) {
            g_T64[(size_t)row*64 + lane]      = tx * dw;
            g_T64[(size_t)row*64 + 32 + lane] = ts * db;
        } else {
            g_T64[(size_t)row*64 + lane]      = 0.f;   // pads 30,31
            g_T64[(size_t)row*64 + 32 + lane] = 0.f;   // pads 62,63
        }
    } else {
        const float* Wx = W3030 + 900;    // conv13
        int l4 = lane < 25 ? lane : 24;
        float tx = 0.f;
        float4 ts4 = make_float4(0.f,0.f,0.f,0.f);
        #pragma unroll 6
        for (int k = 0; k < 30; k++) {
            float xk = __shfl_sync(0xffffffffu, vx, k);
            float sk = __shfl_sync(0xffffffffu, vs, k);
            tx += xk * Wx[k*30 + c];
            float4 w4 = ((const float4*)(Wp13 + k*100))[l4];
            ts4.x += sk*w4.x; ts4.y += sk*w4.y; ts4.z += sk*w4.z; ts4.w += sk*w4.w;
        }
        g_Tx[(size_t)row*32 + lane] = (lane < 30) ? tx * dw : 0.f;
        if (lane < 25) {
            ts4.x *= db; ts4.y *= db; ts4.z *= db; ts4.w *= db;
            ((float4*)g_Ts)[(size_t)row*25 + lane] = ts4;
        }
    }
}

// layer-3 BN apply (elementwise). grid NB*132/256, block 256.
__global__ void k_apply3(const float* __restrict__ gamma30, const float* __restrict__ beta30,
                         const float* __restrict__ gamma100, const float* __restrict__ beta100)
{
    int idx = blockIdx.x*256 + threadIdx.x;
    if (idx >= NB*132) return;
    int row = idx / 132, pc = idx % 132;
    if (pc == 30 || pc == 31) return;
    const float invM = 1.0f / (float)NB;
    float sum = g_stats[256 + pc], sq = g_stats[256 + 132 + pc];
    float mean = sum * invM;
    float var  = fmaxf(sq*invM - mean*mean, 0.f);
    float g, bb;
    if (pc < 30) { g = gamma30[60+pc]; bb = beta30[60+pc]; }
    else         { g = gamma100[pc-32]; bb = beta100[pc-32]; }
    float v = (g_pre132[idx] - mean) * rsqrtf(var + 1e-5f) * g + bb;
    if (pc < 30) g_x13[(size_t)row*30 + pc] = v;
    else         g_s13[(size_t)row*100 + pc - 32] = v;
}

// s1 = [s11|s12|s13] @ Wfc + bfc, softmax. grid NB, block 64.
__global__ void k_s1softmax(const float* __restrict__ Wfc, const float* __restrict__ bfc) {
    int row = blockIdx.x;
    __shared__ float sin[160];
    __shared__ float wmax[2], wsum[2];
    int tid = threadIdx.x;
    int warp = tid >> 5;
    if (tid < 30) { sin[tid] = g_s11[row*30+tid]; sin[30+tid] = g_s12[row*30+tid]; }
    for (int i = tid; i < 100; i += 64) sin[60+i] = g_s13[(size_t)row*100+i];
    __syncthreads();
    float2 z = make_float2(-1e30f, -1e30f);
    if (tid < 50) {
        const float2* W2p = (const float2*)Wfc;
        float2 acc = ((const float2*)bfc)[tid];
        #pragma unroll 8
        for (int k = 0; k < 160; k++) {
            float s = sin[k];
            float2 w = W2p[k*50 + tid];
            acc.x += s*w.x; acc.y += s*w.y;
        }
        z = acc;
    }
    float m = fmaxf(z.x, z.y);
    #pragma unroll
    for (int o = 16; o > 0; o >>= 1) m = fmaxf(m, __shfl_xor_sync(0xffffffffu, m, o));
    if ((tid & 31) == 0) wmax[warp] = m;
    __syncthreads();
    float mx = fmaxf(wmax[0], wmax[1]);
    float ex = 0.f, ey = 0.f;
    if (tid < 50) { ex = expf(z.x - mx); ey = expf(z.y - mx); }
    float s = ex + ey;
    #pragma unroll
    for (int o = 16; o > 0; o >>= 1) s += __shfl_xor_sync(0xffffffffu, s, o);
    if ((tid & 31) == 0) wsum[warp] = s;
    __syncthreads();
    float inv = 1.0f / (wsum[0] + wsum[1]);
    if (tid < 50) ((float2*)g_sm)[(size_t)row*50 + tid] = make_float2(ex*inv, ey*inv);
}

// C[b,m,l] = sum_n s[b,n,m] * B[b,n,l], BK=32
__global__ void k_gemmTN(int mode) {
    int CB = mode == 0 ? 100 : 30;
    const float* Bm = mode == 0 ? g_adjs : g_x13;
    float* C = mode == 0 ? g_p1adj : g_p1x;
    int b = blockIdx.z;
    int m0 = blockIdx.y*16, l0 = blockIdx.x*16;
    int tx = threadIdx.x, ty = threadIdx.y;
    __shared__ float As[32][17], Bs[32][17];
    const float* Ab = g_sm + (size_t)b*Nn*100;
    const float* Bb = Bm  + (size_t)b*Nn*CB;
    float acc = 0.f;
    int am = m0 + tx, bl = l0 + tx;
    for (int n0 = 0; n0 < Nn; n0 += 32) {
        As[ty][tx]    = (am < 100) ? Ab[(n0+ty)*100 + am] : 0.f;
        As[ty+16][tx] = (am < 100) ? Ab[(n0+ty+16)*100 + am] : 0.f;
        Bs[ty][tx]    = (bl < CB) ? Bb[(n0+ty)*CB + bl] : 0.f;
        Bs[ty+16][tx] = (bl < CB) ? Bb[(n0+ty+16)*CB + bl] : 0.f;
        __syncthreads();
        #pragma unroll
        for (int i = 0; i < 32; i++) acc += As[i][ty]*Bs[i][tx];
        __syncthreads();
    }
    int m = m0+ty, l = l0+tx;
    if (m < 100 && l < CB) C[((size_t)b*100 + m)*CB + l] = acc;
}

__global__ void k_A2() {
    int b = blockIdx.x;
    const float* p = g_p1adj + b*10000;
    __shared__ float dinv[100], sflag[100];
    int tid = threadIdx.x;
    if (tid < 100) {
        float s = 0.f;
        float diag = p[tid*100+tid];
        for (int j = 0; j < 100; j++) s += p[tid*100+j];
        float d0 = (diag == 0.f) ? 1.f : 0.f;
        float deg = s + d0;
        dinv[tid] = deg > 0.f ? rsqrtf(deg) : 0.f;
        sflag[tid] = d0;
    }
    __syncthreads();
    for (int idx = tid; idx < 10000; idx += blockDim.x) {
        int i = idx/100, j = idx%100;
        float v = p[idx] + ((i == j) ? sflag[i] : 0.f);
        g_A2[b*10000+idx] = dinv[i]*v*dinv[j];
    }
}

// stage-2 conv with fused BN-in and stats-out. grid (8,5), block 256.
__global__ void k_conv2(int mode,
                        const float* __restrict__ gamma30, const float* __restrict__ beta30,
                        const float* __restrict__ W3030, const float* __restrict__ b30)
{
    const float *in, *W, *bias, *gR = nullptr, *bR = nullptr;
    float* outPre; int useBN, offIn = 0, offOut;
    if (mode == 0) { in=g_p1x;  useBN=0;            outPre=g_pre21; offOut=520; W=W3030+2700; bias=b30+150; }
    else if (mode == 1) { in=g_pre21; useBN=1; offIn=520; gR=gamma30+150; bR=beta30+150;
                          outPre=g_pre22; offOut=580; W=W3030+3600; bias=b30+180; }
    else { in=g_pre22; useBN=1; offIn=580; gR=gamma30+180; bR=beta30+180;
           outPre=g_pre23; offOut=640; W=W3030+4500; bias=b30+210; }
    int b = blockIdx.x, chunk = blockIdx.y;
    __shared__ float shin[3000], shtmp[3000];
    __shared__ float scale[30], shift[30], ss[30], sq[30];
    int tid = threadIdx.x;
    if (tid < 30) {
        ss[tid] = 0.f; sq[tid] = 0.f;
        if (useBN) {
            float sum = g_stats[offIn+tid], q = g_stats[offIn+30+tid];
            float m = sum*(1.f/800.f);
            float v = fmaxf(q*(1.f/800.f) - m*m, 0.f);
            float sc = rsqrtf(v+1e-5f)*gR[tid];
            scale[tid] = sc; shift[tid] = bR[tid] - m*sc;
        } else { scale[tid] = 1.f; shift[tid] = 0.f; }
    }
    __syncthreads();
    for (int idx = tid; idx < 3000; idx += 256) {
        int c = idx % 30;
        shin[idx] = in[b*3000+idx]*scale[c] + shift[c];
    }
    __syncthreads();
    for (int idx = tid; idx < 3000; idx += 256) {
        int j = idx/30, c = idx%30;
        float t = 0.f;
        #pragma unroll 6
        for (int k = 0; k < 30; k++) t += shin[j*30+k]*W[k*30+c];
        shtmp[idx] = t;
    }
    __syncthreads();
    const float* A2b = g_A2 + b*10000;
    for (int idx = tid; idx < 600; idx += 256) {
        int il = idx/30, c = idx%30;
        int i = chunk*20 + il;
        float acc = bias[c];
        const float* arow = A2b + i*100;
        #pragma unroll 4
        for (int j = 0; j < 100; j++) acc += arow[j]*shtmp[j*30+c];
        outPre[b*3000 + i*30 + c] = acc;
        atomicAdd(&ss[c], acc);
        atomicAdd(&sq[c], acc*acc);
    }
    __syncthreads();
    if (tid < 30) {
        atomicAdd(&g_stats[offOut+tid], ss[tid]);
        atomicAdd(&g_stats[offOut+30+tid], sq[tid]);
    }
}

// stage-1 max pool partials. grid (8,16), block 96.
__global__ void k_max1() {
    int b = blockIdx.x, ch = blockIdx.y, c = threadIdx.x;
    if (c >= 90) return;
    int which = c/30, cc = c%30;
    const float* buf = which == 0 ? g_x11 : which == 1 ? g_x12 : g_x13;
    const float* p = buf + ((size_t)b*Nn + ch*128)*30 + cc;
    float m = -3.4e38f;
    #pragma unroll 8
    for (int n = 0; n < 128; n++) m = fmaxf(m, p[n*30]);
    g_part1[(b*16+ch)*90 + c] = m;
}

// final: stage-1 reduce + stage-2 max (lazy BN) + MLP. grid 8, block 192.
__global__ void k_final(const float* __restrict__ W1, const float* __restrict__ b1,
                        const float* __restrict__ W2, const float* __restrict__ b2,
                        const float* __restrict__ gamma30, const float* __restrict__ beta30,
                        float* __restrict__ out)
{
    int b = blockIdx.x, tid = threadIdx.x;
    __shared__ float sh[180];
    __shared__ float hh[50];
    if (tid < 90) {
        float m = -3.4e38f;
        #pragma unroll
        for (int q = 0; q < 16; q++) m = fmaxf(m, g_part1[(b*16+q)*90 + tid]);
        sh[tid] = m;
    } else if (tid >= 96 && tid < 186) {
        int c = tid - 96;
        int which = c/30, cc = c%30;
        const float* buf = which == 0 ? g_pre21 : which == 1 ? g_pre22 : g_pre23;
        int off = 520 + which*60;
        float sum = g_stats[off+cc], q = g_stats[off+30+cc];
        float mn = sum*(1.f/800.f);
        float var = fmaxf(q*(1.f/800.f) - mn*mn, 0.f);
        float g  = gamma30[(5+which)*30+cc];
        float be = beta30 [(5+which)*30+cc];
        float sc = rsqrtf(var+1e-5f)*g;
        float shf = be - mn*sc;
        const float* p = buf + b*3000 + cc;
        float m = -3.4e38f;
        #pragma unroll 4
        for (int k = 0; k < 100; k++) m = fmaxf(m, p[k*30]*sc + shf);
        sh[90+c] = m;
    }
    __syncthreads();
    if (tid < 50) {
        float acc = b1[tid];
        #pragma unroll 4
        for (int k = 0; k < 180; k++) acc += sh[k]*W1[k*50+tid];
        hh[tid] = fmaxf(acc, 0.f);
    }
    __syncthreads();
    if (tid < 6) {
        float acc = b2[tid];
        #pragma unroll
        for (int k = 0; k < 50; k++) acc += hh[k]*W2[k*6+tid];
        out[b*6+tid] = acc;
    }
}

// ---------------- host launch ----------------
extern "C" void kernel_launch(void* const* d_in, const int* in_sizes, int n_in,
                              void* d_out, int out_size) {
    const float* x        = (const float*)d_in[0];
    const float* adj      = (const float*)d_in[1];
    const float* W_in     = (const float*)d_in[2];
    const float* W3030    = (const float*)d_in[3];
    const float* Wp13     = (const float*)d_in[4];
    const float* b30      = (const float*)d_in[5];
    const float* b100     = (const float*)d_in[6];
    const float* Wfc      = (const float*)d_in[7];
    const float* bfc      = (const float*)d_in[8];
    const float* W1       = (const float*)d_in[9];
    const float* b1       = (const float*)d_in[10];
    const float* W2       = (const float*)d_in[11];
    const float* b2       = (const float*)d_in[12];
    const float* gamma30  = (const float*)d_in[13];
    const float* beta30   = (const float*)d_in[14];
    const float* gamma100 = (const float*)d_in[15];
    const float* beta100  = (const float*)d_in[16];
    float* out = (float*)d_out;

    k_build<<<dim3(Nn, Bg), 256>>>(adj, x, W_in);

    // layer 1
    k_spmm60<<<NB/8, 256>>>(b30 + 0, b30 + 90, 0);
    k_apply12<<<NB/8, 256>>>(1, gamma30, beta30, W3030, Wp13);
    // layer 2
    k_spmm60<<<NB/8, 256>>>(b30 + 30, b30 + 120, 128);
    k_apply12<<<NB/8, 256>>>(2, gamma30, beta30, W3030, Wp13);
    // layer 3
    k_spmm130<<<NB/4, 256>>>(b30 + 60, b100);
    k_apply3<<<(NB*132 + 255)/256, 256>>>(gamma30, beta30, gamma100, beta100);

    // assignment softmax, pooling
    k_s1softmax<<<NB, 64>>>(Wfc, bfc);
    k_adjs<<<NB/8, 256>>>();
    k_gemmTN<<<dim3(7, 7, Bg), dim3(16, 16)>>>(0);   // p1_adj
    k_gemmTN<<<dim3(2, 7, Bg), dim3(16, 16)>>>(1);   // p1_x
    k_A2<<<Bg, 128>>>();

    // stage 2
    k_conv2<<<dim3(Bg, 5), 256>>>(0, gamma30, beta30, W3030, b30);
    k_conv2<<<dim3(Bg, 5), 256>>>(1, gamma30, beta30, W3030, b30);
    k_conv2<<<dim3(Bg, 5), 256>>>(2, gamma30, beta30, W3030, b30);

    // readout
    k_max1<<<dim3(Bg, 16), 96>>>();
    k_final<<<Bg, 192>>>(W1, b1, W2, b2, gamma30, beta30, out);
}

// round 13
// speedup vs baseline: 1.5721x; 1.0838x over previous
#include <cuda_runtime.h>
#include <cstdint>

#define Bg 8
#define Nn 2048
#define NB (Bg*Nn)          // 16384 rows
#define MAXD 256            // max degree (mean ~102)

// ---------------- device scratch ----------------
__device__ int2  g_edge[NB*MAXD];     // {col, float_as_int(val)}
__device__ int   g_cnt[NB];
__device__ float g_self[NB];
__device__ float g_dinvw[NB];
__device__ float g_dinvb[NB];

__device__ float g_T64[NB*64];        // layers 1/2 transformed feats, padded [w30,p2 | b30,p2]
__device__ float g_Tx [NB*32];        // layer-3 weighted feats (30 + 2 pad)
__device__ float g_Ts [NB*100];       // layer-3 binary feats (100)
__device__ float g_pre64 [NB*64];     // layers 1/2 pre-BN (padded 64)
__device__ float g_pre132[NB*132];    // layer-3 pre-BN (padded [32|100])

__device__ float g_x11[NB*30], g_x12[NB*30], g_x13[NB*30];
__device__ float g_s11[NB*30], g_s12[NB*30];
__device__ float g_sm [NB*100];
__device__ float g_adjs[NB*100];

__device__ float g_p1x  [Bg*100*30];
__device__ float g_p1adj[Bg*100*100];
__device__ float g_A2   [Bg*100*100];
__device__ float g_pre21[Bg*100*30], g_pre22[Bg*100*30], g_pre23[Bg*100*30];
__device__ float g_part1[Bg*16*90];

// stats: L1 @0 (64 sum + 64 sq), L2 @128, L3 @256 (132+132),
//        S2a @520, S2b @580, S2c @640 (30+30 each)
#define STATS_TOTAL 700
__device__ float g_stats[STATS_TOTAL];

// Build edge list + degrees + fused layer-1 transform + stats zeroing. grid (2048,8), block 256.
__global__ void k_build(const float* __restrict__ adj, const float* __restrict__ x,
                        const float* __restrict__ Win) {
    int i = blockIdx.x, b = blockIdx.y;
    int tid = threadIdx.x;
    if (i == 0 && b == 0) {
        for (int q = tid; q < STATS_TOTAL; q += 256) g_stats[q] = 0.f;
    }
    int row = b*Nn + i;
    const float4* arow4 = (const float4*)(adj + (size_t)row * Nn);
    __shared__ int s_cnt;
    __shared__ float s_diag;
    __shared__ float red[256];
    __shared__ float s_dw, s_db;
    if (tid == 0) { s_cnt = 0; s_diag = 0.f; }
    __syncthreads();
    float wsum = 0.f;
    size_t base = (size_t)row * MAXD;
    for (int j4 = tid; j4 < Nn/4; j4 += 256) {
        float4 a = arow4[j4];
        int j = 4*j4;
        float av[4] = {a.x, a.y, a.z, a.w};
        #pragma unroll
        for (int q = 0; q < 4; q++) {
            int jj = j + q;
            float aa = av[q];
            if (jj == i) s_diag = aa;
            if (aa != 0.f) {
                wsum += aa;
                int pos = atomicAdd(&s_cnt, 1);
                if (pos < MAXD) g_edge[base+pos] = make_int2(jj, __float_as_int(aa));
            }
        }
    }
    red[tid] = wsum;
    __syncthreads();
    for (int s = 128; s > 0; s >>= 1) { if (tid < s) red[tid] += red[tid+s]; __syncthreads(); }
    if (tid == 0) {
        int cnt = s_cnt;
        float d0 = (s_diag == 0.f) ? 1.f : 0.f;
        g_cnt[row]  = cnt < MAXD ? cnt : MAXD;
        g_self[row] = d0;
        float degw = red[0] + d0;
        float degb = (float)cnt + d0;
        float dw = degw > 0.f ? rsqrtf(degw) : 0.f;
        float db = degb > 0.f ? rsqrtf(degb) : 0.f;
        g_dinvw[row] = dw; g_dinvb[row] = db;
        s_dw = dw; s_db = db;
    }
    __syncthreads();
    if (tid < 64) {
        float x0 = x[row*3], x1 = x[row*3+1], x2 = x[row*3+2];
        int c = tid; float t = 0.f;
        if (c < 30) t = (x0*Win[c] + x1*Win[30+c] + x2*Win[60+c]) * s_dw;
        else if (c >= 32 && c < 62) {
            int c2 = c-32;
            t = (x0*Win[90+c2] + x1*Win[120+c2] + x2*Win[150+c2]) * s_db;
        }
        g_T64[(size_t)row*64 + c] = t;
    }
}

__device__ __forceinline__ float chb60(int c, const float* bx, const float* bs) {
    if (c < 30) return bx[c];
    if (c >= 32 && c < 62) return bs[c-32];
    return 0.f;
}

// layers 1/2 dual SpMM: warp-per-row, 4 edges/iter, dual acc, fused stats. grid NB/8, block 256.
__global__ void k_spmm60(const float* __restrict__ biasX, const float* __restrict__ biasS,
                         int statOff) {
    __shared__ float sstat[8][128];
    int tid = threadIdx.x;
    int warp = tid >> 5, lane = tid & 31;
    int row = blockIdx.x*8 + warp;
    int bbase = row & ~(Nn-1);
    const float4* T4 = (const float4*)g_T64;
    int hf = lane >> 4;            // which edge of the pair
    int cl = lane & 15;            // float4 channel group
    float selfv = (hf == 0) ? g_self[row] : 0.f;
    float4 t0 = T4[(size_t)row*16 + cl];
    float4 acc = make_float4(selfv*t0.x, selfv*t0.y, selfv*t0.z, selfv*t0.w);
    float4 acc2 = make_float4(0.f, 0.f, 0.f, 0.f);
    int cnt = g_cnt[row];
    const int2* ep = g_edge + (size_t)row*MAXD;
    int k = 0;
    #pragma unroll 2
    for (; k + 4 <= cnt; k += 4) {
        int2 e0 = ep[k + hf];
        int2 e1 = ep[k + 2 + hf];
        float4 ta = T4[(size_t)(bbase + e0.x)*16 + cl];
        float4 tb = T4[(size_t)(bbase + e1.x)*16 + cl];
        float w0 = (cl < 8) ? __int_as_float(e0.y) : 1.0f;
        float w1 = (cl < 8) ? __int_as_float(e1.y) : 1.0f;
        acc.x  += w0*ta.x; acc.y  += w0*ta.y; acc.z  += w0*ta.z; acc.w  += w0*ta.w;
        acc2.x += w1*tb.x; acc2.y += w1*tb.y; acc2.z += w1*tb.z; acc2.w += w1*tb.w;
    }
    for (; k < cnt; k += 2) {
        int kk = k + hf;
        int2 e = ep[kk < cnt ? kk : (cnt-1)];
        float4 t = T4[(size_t)(bbase + e.x)*16 + cl];
        float w = (kk < cnt) ? ((cl < 8) ? __int_as_float(e.y) : 1.0f) : 0.f;
        acc.x += w*t.x; acc.y += w*t.y; acc.z += w*t.z; acc.w += w*t.w;
    }
    acc.x += acc2.x; acc.y += acc2.y; acc.z += acc2.z; acc.w += acc2.w;
    acc.x += __shfl_xor_sync(0xffffffffu, acc.x, 16);
    acc.y += __shfl_xor_sync(0xffffffffu, acc.y, 16);
    acc.z += __shfl_xor_sync(0xffffffffu, acc.z, 16);
    acc.w += __shfl_xor_sync(0xffffffffu, acc.w, 16);
    if (lane < 16) {
        float dinv = (lane < 8) ? g_dinvw[row] : g_dinvb[row];
        int c0 = 4*lane;
        float4 bs = make_float4(chb60(c0,biasX,biasS), chb60(c0+1,biasX,biasS),
                                chb60(c0+2,biasX,biasS), chb60(c0+3,biasX,biasS));
        float4 o = make_float4(acc.x*dinv+bs.x, acc.y*dinv+bs.y,
                               acc.z*dinv+bs.z, acc.w*dinv+bs.w);
        ((float4*)g_pre64)[(size_t)row*16 + lane] = o;
        sstat[warp][c0+0]=o.x; sstat[warp][c0+1]=o.y; sstat[warp][c0+2]=o.z; sstat[warp][c0+3]=o.w;
        sstat[warp][64+c0+0]=o.x*o.x; sstat[warp][64+c0+1]=o.y*o.y;
        sstat[warp][64+c0+2]=o.z*o.z; sstat[warp][64+c0+3]=o.w*o.w;
    }
    __syncthreads();
    for (int i = tid; i < 128; i += 256) {
        float s = 0.f;
        #pragma unroll
        for (int wq = 0; wq < 8; wq++) s += sstat[wq][i];
        atomicAdd(&g_stats[statOff + i], s);
    }
}

// layer-3 dual SpMM: 2 warps/row. role0 weighted 32ch, 4 edges/iter; role1 binary 100ch dual-acc.
// grid NB/4, block 256.
__global__ void k_spmm130(const float* __restrict__ biasX, const float* __restrict__ biasS) {
    __shared__ float sstat[264];
    int tid = threadIdx.x;
    for (int i = tid; i < 264; i += 256) sstat[i] = 0.f;
    __syncthreads();
    int warp = tid >> 5, lane = tid & 31;
    int row = blockIdx.x*4 + (warp >> 1);
    int role = warp & 1;
    int bbase = row & ~(Nn-1);
    int cnt = g_cnt[row];
    const int2* ep = g_edge + (size_t)row*MAXD;
    if (role == 0) {
        const float4* T4 = (const float4*)g_Tx;
        int qt = lane >> 3;        // which edge of the quad
        int cl = lane & 7;
        float selfv = (qt == 0) ? g_self[row] : 0.f;
        float4 t0 = T4[(size_t)row*8 + cl];
        float4 acc = make_float4(selfv*t0.x, selfv*t0.y, selfv*t0.z, selfv*t0.w);
        #pragma unroll 2
        for (int k = 0; k < cnt; k += 4) {
            int kk = k + qt;
            int2 e = ep[kk < cnt ? kk : (cnt-1)];
            float4 t = T4[(size_t)(bbase + e.x)*8 + cl];
            float w = (kk < cnt) ? __int_as_float(e.y) : 0.f;
            acc.x += w*t.x; acc.y += w*t.y; acc.z += w*t.z; acc.w += w*t.w;
        }
        acc.x += __shfl_xor_sync(0xffffffffu, acc.x, 8);
        acc.y += __shfl_xor_sync(0xffffffffu, acc.y, 8);
        acc.z += __shfl_xor_sync(0xffffffffu, acc.z, 8);
        acc.w += __shfl_xor_sync(0xffffffffu, acc.w, 8);
        acc.x += __shfl_xor_sync(0xffffffffu, acc.x, 16);
        acc.y += __shfl_xor_sync(0xffffffffu, acc.y, 16);
        acc.z += __shfl_xor_sync(0xffffffffu, acc.z, 16);
        acc.w += __shfl_xor_sync(0xffffffffu, acc.w, 16);
        if (lane < 8) {
            float dinv = g_dinvw[row];
            int c0 = 4*lane;
            float4 bs = make_float4(c0<30?biasX[c0]:0.f, c0+1<30?biasX[c0+1]:0.f,
                                    c0+2<30?biasX[c0+2]:0.f, c0+3<30?biasX[c0+3]:0.f);
            float4 o = make_float4(acc.x*dinv+bs.x, acc.y*dinv+bs.y,
                                   acc.z*dinv+bs.z, acc.w*dinv+bs.w);
            ((float4*)g_pre132)[(size_t)row*33 + lane] = o;
            atomicAdd(&sstat[c0+0], o.x); atomicAdd(&sstat[c0+1], o.y);
            atomicAdd(&sstat[c0+2], o.z); atomicAdd(&sstat[c0+3], o.w);
            atomicAdd(&sstat[132+c0+0], o.x*o.x); atomicAdd(&sstat[132+c0+1], o.y*o.y);
            atomicAdd(&sstat[132+c0+2], o.z*o.z); atomicAdd(&sstat[132+c0+3], o.w*o.w);
        }
    } else {
        const float4* S4 = (const float4*)g_Ts;
        int cl = lane < 24 ? lane : 24;
        float selfv = g_self[row];
        float4 t0 = S4[(size_t)row*25 + cl];
        float4 acc = make_float4(selfv*t0.x, selfv*t0.y, selfv*t0.z, selfv*t0.w);
        float4 acc2 = make_float4(0.f, 0.f, 0.f, 0.f);
        int k = 0;
        #pragma unroll 2
        for (; k + 2 <= cnt; k += 2) {
            int2 e0 = ep[k];
            int2 e1 = ep[k+1];
            float4 ta = S4[(size_t)(bbase + e0.x)*25 + cl];
            float4 tb = S4[(size_t)(bbase + e1.x)*25 + cl];
            acc.x  += ta.x; acc.y  += ta.y; acc.z  += ta.z; acc.w  += ta.w;
            acc2.x += tb.x; acc2.y += tb.y; acc2.z += tb.z; acc2.w += tb.w;
        }
        if (k < cnt) {
            int2 e = ep[k];
            float4 t = S4[(size_t)(bbase + e.x)*25 + cl];
            acc.x += t.x; acc.y += t.y; acc.z += t.z; acc.w += t.w;
        }
        acc.x += acc2.x; acc.y += acc2.y; acc.z += acc2.z; acc.w += acc2.w;
        if (lane < 25) {
            float dinv = g_dinvb[row];
            float4 bs = ((const float4*)biasS)[lane];
            float4 o = make_float4(acc.x*dinv+bs.x, acc.y*dinv+bs.y,
                                   acc.z*dinv+bs.z, acc.w*dinv+bs.w);
            ((float4*)g_pre132)[(size_t)row*33 + 8 + lane] = o;
            int c0 = 32 + 4*lane;
            atomicAdd(&sstat[c0+0], o.x); atomicAdd(&sstat[c0+1], o.y);
            atomicAdd(&sstat[c0+2], o.z); atomicAdd(&sstat[c0+3], o.w);
            atomicAdd(&sstat[132+c0+0], o.x*o.x); atomicAdd(&sstat[132+c0+1], o.y*o.y);
            atomicAdd(&sstat[132+c0+2], o.z*o.z); atomicAdd(&sstat[132+c0+3], o.w*o.w);
        }
    }
    __syncthreads();
    for (int i = tid; i < 264; i += 256) atomicAdd(&g_stats[256 + i], sstat[i]);
}

// adj @ s, warp-per-row float4, dual-edge dual-acc. grid NB/8, block 256.
__global__ void k_adjs() {
    int tid = threadIdx.x;
    int warp = tid >> 5, lane = tid & 31;
    int row = blockIdx.x*8 + warp;
    int bbase = row & ~(Nn-1);
    const float4* S4 = (const float4*)g_sm;
    int cl = lane < 24 ? lane : 24;
    float4 acc = make_float4(0.f, 0.f, 0.f, 0.f);
    float4 acc2 = make_float4(0.f, 0.f, 0.f, 0.f);
    int cnt = g_cnt[row];
    const int2* ep = g_edge + (size_t)row*MAXD;
    int k = 0;
    #pragma unroll 2
    for (; k + 2 <= cnt; k += 2) {
        int2 e0 = ep[k];
        int2 e1 = ep[k+1];
        float4 ta = S4[(size_t)(bbase + e0.x)*25 + cl];
        float4 tb = S4[(size_t)(bbase + e1.x)*25 + cl];
        float w0 = __int_as_float(e0.y);
        float w1 = __int_as_float(e1.y);
        acc.x  += w0*ta.x; acc.y  += w0*ta.y; acc.z  += w0*ta.z; acc.w  += w0*ta.w;
        acc2.x += w1*tb.x; acc2.y += w1*tb.y; acc2.z += w1*tb.z; acc2.w += w1*tb.w;
    }
    if (k < cnt) {
        int2 e = ep[k];
        float4 t = S4[(size_t)(bbase + e.x)*25 + cl];
        float w = __int_as_float(e.y);
        acc.x += w*t.x; acc.y += w*t.y; acc.z += w*t.z; acc.w += w*t.w;
    }
    acc.x += acc2.x; acc.y += acc2.y; acc.z += acc2.z; acc.w += acc2.w;
    if (lane < 25) ((float4*)g_adjs)[(size_t)row*25 + lane] = acc;
}

// layers 1/2: warp-per-row BN-apply + next-layer transform via shuffles. grid NB/8, block 256.
__global__ void k_apply12(int layer,
                          const float* __restrict__ gamma30, const float* __restrict__ beta30,
                          const float* __restrict__ W3030, const float* __restrict__ Wp13)
{
    int tid = threadIdx.x;
    int warp = tid >> 5, lane = tid & 31;
    int row = blockIdx.x*8 + warp;
    const float invM = 1.0f / (float)NB;
    int off; const float *gX, *bX, *gS, *bS; float *outX, *outS;
    if (layer == 1) {
        off=0;   gX=gamma30;    bX=beta30;    gS=gamma30+90;  bS=beta30+90;
        outX=g_x11; outS=g_s11;
    } else {
        off=128; gX=gamma30+30; bX=beta30+30; gS=gamma30+120; bS=beta30+120;
        outX=g_x12; outS=g_s12;
    }
    int c = lane < 30 ? lane : 29;   // clamp for shuffle-safety
    // BN x-branch
    float sumx = g_stats[off + c], sqx = g_stats[off + 64 + c];
    float mx = sumx * invM;
    float vrx = fmaxf(sqx*invM - mx*mx, 0.f);
    float vx = (g_pre64[(size_t)row*64 + c] - mx) * rsqrtf(vrx + 1e-5f) * gX[c] + bX[c];
    // BN s-branch
    float sums = g_stats[off + 32 + c], sqs = g_stats[off + 64 + 32 + c];
    float ms = sums * invM;
    float vrs = fmaxf(sqs*invM - ms*ms, 0.f);
    float vs = (g_pre64[(size_t)row*64 + 32 + c] - ms) * rsqrtf(vrs + 1e-5f) * gS[c] + bS[c];
    if (lane < 30) {
        outX[(size_t)row*30 + lane] = vx;
        outS[(size_t)row*30 + lane] = vs;
    }
    float dw = g_dinvw[row], db = g_dinvb[row];
    if (layer == 1) {
        const float* Wx = W3030;          // conv12
        const float* Ws = W3030 + 1800;   // pool_conv12
        float tx = 0.f, ts = 0.f;
        #pragma unroll 6
        for (int k = 0; k < 30; k++) {
            float xk = __shfl_sync(0xffffffffu, vx, k);
            float sk = __shfl_sync(0xffffffffu, vs, k);
            tx += xk * Wx[k*30 + c];
            ts += sk * Ws[k*30 + c];
        }
        if (lane < 30) {
            g_T64[(size_t)row*64 + lane]      = tx * dw;
            g_T64[(size_t)row*64 + 32 + lane] = ts * db;
        } else {
            g_T64[(size_t)row*64 + lane]      = 0.f;   // pads 30,31
            g_T64[(size_t)row*64 + 32 + lane] = 0.f;   // pads 62,63
        }
    } else {
        const float* Wx = W3030 + 900;    // conv13
        int l4 = lane < 25 ? lane : 24;
        float tx = 0.f;
        float4 ts4 = make_float4(0.f,0.f,0.f,0.f);
        #pragma unroll 6
        for (int k = 0; k < 30; k++) {
            float xk = __shfl_sync(0xffffffffu, vx, k);
            float sk = __shfl_sync(0xffffffffu, vs, k);
            tx += xk * Wx[k*30 + c];
            float4 w4 = ((const float4*)(Wp13 + k*100))[l4];
            ts4.x += sk*w4.x; ts4.y += sk*w4.y; ts4.z += sk*w4.z; ts4.w += sk*w4.w;
        }
        g_Tx[(size_t)row*32 + lane] = (lane < 30) ? tx * dw : 0.f;
        if (lane < 25) {
            ts4.x *= db; ts4.y *= db; ts4.z *= db; ts4.w *= db;
            ((float4*)g_Ts)[(size_t)row*25 + lane] = ts4;
        }
    }
}

// layer-3 BN apply for the x-branch only. grid NB*30/256, block 256.
__global__ void k_applyx3(const float* __restrict__ gamma30, const float* __restrict__ beta30)
{
    int idx = blockIdx.x*256 + threadIdx.x;
    if (idx >= NB*30) return;
    int row = idx / 30, c = idx % 30;
    const float invM = 1.0f / (float)NB;
    float sum = g_stats[256 + c], sq = g_stats[256 + 132 + c];
    float mean = sum * invM;
    float var  = fmaxf(sq*invM - mean*mean, 0.f);
    float v = (g_pre132[(size_t)row*132 + c] - mean) * rsqrtf(var + 1e-5f) * gamma30[60+c] + beta30[60+c];
    g_x13[idx] = v;
}

// assignment GEMM + softmax, register-blocked, s13-BN fused inline.
// grid NB/64, block 256. thread = (rg 0..15: 4 rows) x (cg 0..15: 7 cols)
__global__ void k_assign(const float* __restrict__ Wfc, const float* __restrict__ bfc,
                         const float* __restrict__ gamma100, const float* __restrict__ beta100)
{
    __shared__ float Wsh[32][100];
    __shared__ float ssh[64][33];
    __shared__ float sc100[100], sf100[100];
    int tid = threadIdx.x;
    int row0 = blockIdx.x * 64;
    if (tid < 100) {
        const float invM = 1.0f / (float)NB;
        int pc = 32 + tid;
        float sum = g_stats[256+pc], sq = g_stats[256+132+pc];
        float mean = sum*invM;
        float var = fmaxf(sq*invM - mean*mean, 0.f);
        float s = rsqrtf(var+1e-5f)*gamma100[tid];
        sc100[tid] = s; sf100[tid] = beta100[tid] - mean*s;
    }
    int rg = tid >> 4;      // 0..15
    int cg = tid & 15;      // 0..15
    float acc[4][7];
    #pragma unroll
    for (int i = 0; i < 4; i++)
        #pragma unroll
        for (int j = 0; j < 7; j++) acc[i][j] = 0.f;
    __syncthreads();
    for (int k0 = 0; k0 < 160; k0 += 32) {
        for (int idx = tid; idx < 3200; idx += 256) {
            int kk = idx/100, cc = idx - kk*100;
            Wsh[kk][cc] = Wfc[(k0+kk)*100 + cc];
        }
        for (int idx = tid; idx < 2048; idx += 256) {
            int r = idx >> 5, kk = idx & 31;
            int k = k0 + kk;
            int row = row0 + r;
            float v;
            if (k < 30)      v = g_s11[row*30 + k];
            else if (k < 60) v = g_s12[row*30 + k - 30];
            else {
                int cc = k - 60;
                v = g_pre132[(size_t)row*132 + 32 + cc]*sc100[cc] + sf100[cc];
            }
            ssh[r][kk] = v;
        }
        __syncthreads();
        #pragma unroll 4
        for (int kk = 0; kk < 32; kk++) {
            float w[7];
            #pragma unroll
            for (int j = 0; j < 7; j++) {
                int cc = cg*7 + j;
                w[j] = (cc < 100) ? Wsh[kk][cc] : 0.f;
            }
            #pragma unroll
            for (int i = 0; i < 4; i++) {
                float sv = ssh[rg*4 + i][kk];
                #pragma unroll
                for (int j = 0; j < 7; j++) acc[i][j] += sv*w[j];
            }
        }
        __syncthreads();
    }
    // bias + row softmax (16 threads per row-group share a 16-lane shuffle span)
    float z[4][7];
    #pragma unroll
    for (int i = 0; i < 4; i++)
        #pragma unroll
        for (int j = 0; j < 7; j++) {
            int cc = cg*7 + j;
            z[i][j] = (cc < 100) ? acc[i][j] + bfc[cc] : -1e30f;
        }
    #pragma unroll
    for (int i = 0; i < 4; i++) {
        float m = -1e30f;
        #pragma unroll
        for (int j = 0; j < 7; j++) m = fmaxf(m, z[i][j]);
        #pragma unroll
        for (int o = 8; o > 0; o >>= 1) m = fmaxf(m, __shfl_xor_sync(0xffffffffu, m, o));
        float s = 0.f;
        #pragma unroll
        for (int j = 0; j < 7; j++) {
            int cc = cg*7 + j;
            z[i][j] = (cc < 100) ? expf(z[i][j] - m) : 0.f;
            s += z[i][j];
        }
        #pragma unroll
        for (int o = 8; o > 0; o >>= 1) s += __shfl_xor_sync(0xffffffffu, s, o);
        float inv = 1.0f / s;
        int row = row0 + rg*4 + i;
        #pragma unroll
        for (int j = 0; j < 7; j++) {
            int cc = cg*7 + j;
            if (cc < 100) g_sm[(size_t)row*100 + cc] = z[i][j]*inv;
        }
    }
}

// C[b,m,l] = sum_n s[b,n,m] * B[b,n,l], BK=32
__global__ void k_gemmTN(int mode) {
    int CB = mode == 0 ? 100 : 30;
    const float* Bm = mode == 0 ? g_adjs : g_x13;
    float* C = mode == 0 ? g_p1adj : g_p1x;
    int b = blockIdx.z;
    int m0 = blockIdx.y*16, l0 = blockIdx.x*16;
    int tx = threadIdx.x, ty = threadIdx.y;
    __shared__ float As[32][17], Bs[32][17];
    const float* Ab = g_sm + (size_t)b*Nn*100;
    const float* Bb = Bm  + (size_t)b*Nn*CB;
    float acc = 0.f;
    int am = m0 + tx, bl = l0 + tx;
    for (int n0 = 0; n0 < Nn; n0 += 32) {
        As[ty][tx]    = (am < 100) ? Ab[(n0+ty)*100 + am] : 0.f;
        As[ty+16][tx] = (am < 100) ? Ab[(n0+ty+16)*100 + am] : 0.f;
        Bs[ty][tx]    = (bl < CB) ? Bb[(n0+ty)*CB + bl] : 0.f;
        Bs[ty+16][tx] = (bl < CB) ? Bb[(n0+ty+16)*CB + bl] : 0.f;
        __syncthreads();
        #pragma unroll
        for (int i = 0; i < 32; i++) acc += As[i][ty]*Bs[i][tx];
        __syncthreads();
    }
    int m = m0+ty, l = l0+tx;
    if (m < 100 && l < CB) C[((size_t)b*100 + m)*CB + l] = acc;
}

__global__ void k_A2() {
    int b = blockIdx.x;
    const float* p = g_p1adj + b*10000;
    __shared__ float dinv[100], sflag[100];
    int tid = threadIdx.x;
    if (tid < 100) {
        float s = 0.f;
        float diag = p[tid*100+tid];
        for (int j = 0; j < 100; j++) s += p[tid*100+j];
        float d0 = (diag == 0.f) ? 1.f : 0.f;
        float deg = s + d0;
        dinv[tid] = deg > 0.f ? rsqrtf(deg) : 0.f;
        sflag[tid] = d0;
    }
    __syncthreads();
    for (int idx = tid; idx < 10000; idx += blockDim.x) {
        int i = idx/100, j = idx%100;
        float v = p[idx] + ((i == j) ? sflag[i] : 0.f);
        g_A2[b*10000+idx] = dinv[i]*v*dinv[j];
    }
}

// stage-2 conv with fused BN-in and stats-out. grid (8,5), block 256.
__global__ void k_conv2(int mode,
                        const float* __restrict__ gamma30, const float* __restrict__ beta30,
                        const float* __restrict__ W3030, const float* __restrict__ b30)
{
    const float *in, *W, *bias, *gR = nullptr, *bR = nullptr;
    float* outPre; int useBN, offIn = 0, offOut;
    if (mode == 0) { in=g_p1x;  useBN=0;            outPre=g_pre21; offOut=520; W=W3030+2700; bias=b30+150; }
    else if (mode == 1) { in=g_pre21; useBN=1; offIn=520; gR=gamma30+150; bR=beta30+150;
                          outPre=g_pre22; offOut=580; W=W3030+3600; bias=b30+180; }
    else { in=g_pre22; useBN=1; offIn=580; gR=gamma30+180; bR=beta30+180;
           outPre=g_pre23; offOut=640; W=W3030+4500; bias=b30+210; }
    int b = blockIdx.x, chunk = blockIdx.y;
    __shared__ float shin[3000], shtmp[3000];
    __shared__ float scale[30], shift[30], ss[30], sq[30];
    int tid = threadIdx.x;
    if (tid < 30) {
        ss[tid] = 0.f; sq[tid] = 0.f;
        if (useBN) {
            float sum = g_stats[offIn+tid], q = g_stats[offIn+30+tid];
            float m = sum*(1.f/800.f);
            float v = fmaxf(q*(1.f/800.f) - m*m, 0.f);
            float sc = rsqrtf(v+1e-5f)*gR[tid];
            scale[tid] = sc; shift[tid] = bR[tid] - m*sc;
        } else { scale[tid] = 1.f; shift[tid] = 0.f; }
    }
    __syncthreads();
    for (int idx = tid; idx < 3000; idx += 256) {
        int c = idx % 30;
        shin[idx] = in[b*3000+idx]*scale[c] + shift[c];
    }
    __syncthreads();
    for (int idx = tid; idx < 3000; idx += 256) {
        int j = idx/30, c = idx%30;
        float t = 0.f;
        #pragma unroll 6
        for (int k = 0; k < 30; k++) t += shin[j*30+k]*W[k*30+c];
        shtmp[idx] = t;
    }
    __syncthreads();
    const float* A2b = g_A2 + b*10000;
    for (int idx = tid; idx < 600; idx += 256) {
        int il = idx/30, c = idx%30;
        int i = chunk*20 + il;
        float acc = bias[c];
        const float* arow = A2b + i*100;
        #pragma unroll 4
        for (int j = 0; j < 100; j++) acc += arow[j]*shtmp[j*30+c];
        outPre[b*3000 + i*30 + c] = acc;
        atomicAdd(&ss[c], acc);
        atomicAdd(&sq[c], acc*acc);
    }
    __syncthreads();
    if (tid < 30) {
        atomicAdd(&g_stats[offOut+tid], ss[tid]);
        atomicAdd(&g_stats[offOut+30+tid], sq[tid]);
    }
}

// stage-1 max pool partials. grid (8,16), block 96.
__global__ void k_max1() {
    int b = blockIdx.x, ch = blockIdx.y, c = threadIdx.x;
    if (c >= 90) return;
    int which = c/30, cc = c%30;
    const float* buf = which == 0 ? g_x11 : which == 1 ? g_x12 : g_x13;
    const float* p = buf + ((size_t)b*Nn + ch*128)*30 + cc;
    float m = -3.4e38f;
    #pragma unroll 8
    for (int n = 0; n < 128; n++) m = fmaxf(m, p[n*30]);
    g_part1[(b*16+ch)*90 + c] = m;
}

// final: stage-1 reduce + stage-2 max (lazy BN) + MLP. grid 8, block 192.
__global__ void k_final(const float* __restrict__ W1, const float* __restrict__ b1,
                        const float* __restrict__ W2, const float* __restrict__ b2,
                        const float* __restrict__ gamma30, const float* __restrict__ beta30,
                        float* __restrict__ out)
{
    int b = blockIdx.x, tid = threadIdx.x;
    __shared__ float sh[180];
    __shared__ float hh[50];
    if (tid < 90) {
        float m = -3.4e38f;
        #pragma unroll
        for (int q = 0; q < 16; q++) m = fmaxf(m, g_part1[(b*16+q)*90 + tid]);
        sh[tid] = m;
    } else if (tid >= 96 && tid < 186) {
        int c = tid - 96;
        int which = c/30, cc = c%30;
        const float* buf = which == 0 ? g_pre21 : which == 1 ? g_pre22 : g_pre23;
        int off = 520 + which*60;
        float sum = g_stats[off+cc], q = g_stats[off+30+cc];
        float mn = sum*(1.f/800.f);
        float var = fmaxf(q*(1.f/800.f) - mn*mn, 0.f);
        float g  = gamma30[(5+which)*30+cc];
        float be = beta30 [(5+which)*30+cc];
        float sc = rsqrtf(var+1e-5f)*g;
        float shf = be - mn*sc;
        const float* p = buf + b*3000 + cc;
        float m = -3.4e38f;
        #pragma unroll 4
        for (int k = 0; k < 100; k++) m = fmaxf(m, p[k*30]*sc + shf);
        sh[90+c] = m;
    }
    __syncthreads();
    if (tid < 50) {
        float acc = b1[tid];
        #pragma unroll 4
        for (int k = 0; k < 180; k++) acc += sh[k]*W1[k*50+tid];
        hh[tid] = fmaxf(acc, 0.f);
    }
    __syncthreads();
    if (tid < 6) {
        float acc = b2[tid];
        #pragma unroll
        for (int k = 0; k < 50; k++) acc += hh[k]*W2[k*6+tid];
        out[b*6+tid] = acc;
    }
}

// ---------------- host launch ----------------
extern "C" void kernel_launch(void* const* d_in, const int* in_sizes, int n_in,
                              void* d_out, int out_size) {
    const float* x        = (const float*)d_in[0];
    const float* adj      = (const float*)d_in[1];
    const float* W_in     = (const float*)d_in[2];
    const float* W3030    = (const float*)d_in[3];
    const float* Wp13     = (const float*)d_in[4];
    const float* b30      = (const float*)d_in[5];
    const float* b100     = (const float*)d_in[6];
    const float* Wfc      = (const float*)d_in[7];
    const float* bfc      = (const float*)d_in[8];
    const float* W1       = (const float*)d_in[9];
    const float* b1       = (const float*)d_in[10];
    const float* W2       = (const float*)d_in[11];
    const float* b2       = (const float*)d_in[12];
    const float* gamma30  = (const float*)d_in[13];
    const float* beta30   = (const float*)d_in[14];
    const float* gamma100 = (const float*)d_in[15];
    const float* beta100  = (const float*)d_in[16];
    float* out = (float*)d_out;

    k_build<<<dim3(Nn, Bg), 256>>>(adj, x, W_in);

    // layer 1
    k_spmm60<<<NB/8, 256>>>(b30 + 0, b30 + 90, 0);
    k_apply12<<<NB/8, 256>>>(1, gamma30, beta30, W3030, Wp13);
    // layer 2
    k_spmm60<<<NB/8, 256>>>(b30 + 30, b30 + 120, 128);
    k_apply12<<<NB/8, 256>>>(2, gamma30, beta30, W3030, Wp13);
    // layer 3
    k_spmm130<<<NB/4, 256>>>(b30 + 60, b100);
    k_applyx3<<<(NB*30 + 255)/256, 256>>>(gamma30, beta30);

    // assignment (GEMM + softmax, s13-BN fused), pooling
    k_assign<<<NB/64, 256>>>(Wfc, bfc, gamma100, beta100);
    k_adjs<<<NB/8, 256>>>();
    k_gemmTN<<<dim3(7, 7, Bg), dim3(16, 16)>>>(0);   // p1_adj
    k_gemmTN<<<dim3(2, 7, Bg), dim3(16, 16)>>>(1);   // p1_x
    k_A2<<<Bg, 128>>>();

    // stage 2
    k_conv2<<<dim3(Bg, 5), 256>>>(0, gamma30, beta30, W3030, b30);
    k_conv2<<<dim3(Bg, 5), 256>>>(1, gamma30, beta30, W3030, b30);
    k_conv2<<<dim3(Bg, 5), 256>>>(2, gamma30, beta30, W3030, b30);

    // readout
    k_max1<<<dim3(Bg, 16), 96>>>();
    k_final<<<Bg, 192>>>(W1, b1, W2, b2, gamma30, beta30, out);
}